// round 2
// baseline (speedup 1.0000x reference)
#include <cuda_runtime.h>
#include <math.h>

// Problem constants
constexpr int NB   = 128;    // batch
constexpr int NP   = 196;    // num patches
constexpr int FEAT = 2048;   // image feature dim
constexpr int E    = 512;    // embedding dim
constexpr int D    = 512;    // hidden dim
constexpr int V    = 10000;  // vocab
constexpr int L    = 52;     // caption length
constexpr int T    = 51;     // decode steps (L-1)
constexpr int G    = 4 * D;  // gates width 2048
constexpr int R    = NB * T; // 6528 rows

// -------- device scratch (static allocation only; no cudaMalloc allowed) ----
__device__ float d_fm[NB * FEAT];      // sorted mean features
__device__ float d_hst[NB * D];        // h state
__device__ float d_cst[NB * D];        // c state
__device__ float d_gates[NB * G];      // per-step gates
__device__ float d_xproj[(size_t)R * G]; // precomputed x@Wih^T + biases (53.5MB)
__device__ float d_Hbuf[(size_t)R * D];  // h_new per (b,t) for word projection
__device__ int   d_sortind[NB];
__device__ int   d_dlen[NB];
__device__ int   d_tok[R];
__device__ float d_bias2[G];           // b_ih + b_hh

// ---------------------------------------------------------------------------
// prep: stable descending argsort (counting), dec_len, token gather,
// bias sum, c-state zero, and the int-output tail of d_out (as float).
// ---------------------------------------------------------------------------
__global__ void prep_kernel(const int* __restrict__ clen,
                            const int* __restrict__ caps,
                            const float* __restrict__ b_ih,
                            const float* __restrict__ b_hh,
                            float* __restrict__ out,
                            int write_tail)
{
    __shared__ int s_len[NB];
    int tid = threadIdx.x;
    s_len[tid] = clen[tid];          // caption_lengths is (B,1)
    __syncthreads();
    int li = s_len[tid];
    int rank = 0;
    #pragma unroll 4
    for (int j = 0; j < NB; j++) {
        int lj = s_len[j];
        rank += (lj > li) || (lj == li && j < tid);
    }
    d_sortind[rank] = tid;           // sort_ind[rank] = tid
    __syncthreads();

    int src = d_sortind[tid];
    int dl  = s_len[src] - 1;
    d_dlen[tid] = dl;

    if (write_tail) {
        float* out_caps = out + (size_t)NB * T * V;
        float* out_dlen = out_caps + (size_t)NB * L;
        float* out_sort = out_dlen + NB;
        out_dlen[tid] = (float)dl;
        out_sort[tid] = (float)src;
        for (int j = 0; j < L; j++) {
            int tk = caps[src * L + j];
            out_caps[tid * L + j] = (float)tk;
            if (j < T) d_tok[tid * T + j] = tk;
        }
    } else {
        for (int j = 0; j < T; j++)
            d_tok[tid * T + j] = caps[src * L + j];
    }

    for (int j = tid; j < G; j += NB)      d_bias2[j] = b_ih[j] + b_hh[j];
    for (int j = tid; j < NB * D; j += NB) d_cst[j] = 0.f;
}

// ---------------------------------------------------------------------------
// mean over patches, applying the sort permutation. One block per output row.
// ---------------------------------------------------------------------------
__global__ void mean_kernel(const float* __restrict__ feats)
{
    int b   = blockIdx.x;
    int src = d_sortind[b];
    const float* base = feats + (size_t)src * NP * FEAT;
    int tid = threadIdx.x;  // 256
    float acc[FEAT / 256];
    #pragma unroll
    for (int j = 0; j < FEAT / 256; j++) acc[j] = 0.f;
    for (int p = 0; p < NP; p++) {
        const float* row = base + (size_t)p * FEAT;
        #pragma unroll
        for (int j = 0; j < FEAT / 256; j++) acc[j] += __ldg(&row[tid + j * 256]);
    }
    #pragma unroll
    for (int j = 0; j < FEAT / 256; j++)
        d_fm[b * FEAT + tid + j * 256] = acc[j] * (1.f / NP);
}

// ---------------------------------------------------------------------------
// Generic C[M,N] = A[M,K] @ B[N,K]^T (+bias[N]) (+Cin) with optional A-row
// gather and optional row-mask (word projection). BM = 16*TM, BN = 64.
// M must be a multiple of BM, K a multiple of 32 (true for all call sites).
// ---------------------------------------------------------------------------
template<int TM>
__global__ void gemm_tn(const float* __restrict__ A, int lda,
                        const int*   __restrict__ aIdx,
                        const float* __restrict__ Bm,
                        const float* __restrict__ bias,
                        const float* __restrict__ Cin, int ldcin,
                        float* __restrict__ Cout, int ldc,
                        int N, int K,
                        const int* __restrict__ dlen)
{
    constexpr int BM = 16 * TM;
    constexpr int BN = 64;
    __shared__ float As[32][BM + 1];
    __shared__ float Bs[32][BN + 1];
    __shared__ int s_any;

    int tid = threadIdx.x;              // 256 threads
    int m0  = blockIdx.x * BM;
    int n0  = blockIdx.y * BN;
    int tx  = tid & 15;
    int ty  = tid >> 4;

    bool maskMode = (dlen != nullptr);
    if (maskMode) {
        if (tid == 0) s_any = 0;
        __syncthreads();
        if (tid < BM) {
            int r = m0 + tid;
            int b = r / T;
            int t = r - b * T;
            if (t < __ldg(&dlen[b])) s_any = 1;
        }
        __syncthreads();
        if (!s_any) {   // whole tile masked: zero-fill, skip GEMM
            #pragma unroll
            for (int i = 0; i < TM; i++) {
                int gm = m0 + ty * TM + i;
                #pragma unroll
                for (int j = 0; j < 4; j++) {
                    int gn = n0 + tx * 4 + j;
                    if (gn < N) Cout[(size_t)gm * ldc + gn] = 0.f;
                }
            }
            return;
        }
    }

    float acc[TM][4];
    #pragma unroll
    for (int i = 0; i < TM; i++)
        #pragma unroll
        for (int j = 0; j < 4; j++) acc[i][j] = 0.f;

    for (int k0 = 0; k0 < K; k0 += 32) {
        #pragma unroll
        for (int i = 0; i < (BM * 32) / 256; i++) {
            int lin = tid + i * 256;
            int m = lin >> 5, k = lin & 31;
            int gm = m0 + m;
            int ar = aIdx ? __ldg(&aIdx[gm]) : gm;
            As[k][m] = __ldg(&A[(size_t)ar * lda + k0 + k]);
        }
        #pragma unroll
        for (int i = 0; i < 8; i++) {
            int lin = tid + i * 256;
            int n = lin >> 5, k = lin & 31;
            int gn = n0 + n;
            Bs[k][n] = (gn < N) ? __ldg(&Bm[(size_t)gn * K + k0 + k]) : 0.f;
        }
        __syncthreads();
        #pragma unroll
        for (int k = 0; k < 32; k++) {
            float bv[4];
            #pragma unroll
            for (int j = 0; j < 4; j++) bv[j] = Bs[k][tx * 4 + j];
            #pragma unroll
            for (int i = 0; i < TM; i++) {
                float av = As[k][ty * TM + i];
                #pragma unroll
                for (int j = 0; j < 4; j++)
                    acc[i][j] = fmaf(av, bv[j], acc[i][j]);
            }
        }
        __syncthreads();
    }

    #pragma unroll
    for (int i = 0; i < TM; i++) {
        int gm = m0 + ty * TM + i;
        bool ok = true;
        if (maskMode) {
            int b = gm / T;
            int t = gm - b * T;
            ok = (t < __ldg(&dlen[b]));
        }
        const float* cin = Cin ? (Cin + (size_t)gm * ldcin) : nullptr;
        #pragma unroll
        for (int j = 0; j < 4; j++) {
            int gn = n0 + tx * 4 + j;
            if (gn < N) {
                float v = acc[i][j];
                if (bias) v += __ldg(&bias[gn]);
                if (cin)  v += cin[gn];
                if (maskMode && !ok) v = 0.f;
                Cout[(size_t)gm * ldc + gn] = v;
            }
        }
    }
}

// ---------------------------------------------------------------------------
// LSTM pointwise: gates -> (i,f,g,o) -> c_new,h_new, masked state update,
// h_new stored to Hbuf for the batched word projection.
// ---------------------------------------------------------------------------
__device__ __forceinline__ float sigmoidf_(float x) {
    return 1.f / (1.f + __expf(-x));
}

__global__ void lstm_pointwise(int t)
{
    int idx = blockIdx.x * blockDim.x + threadIdx.x;  // 65536 = 128*512
    int b = idx >> 9;
    int d = idx & (D - 1);
    const float* g = d_gates + (size_t)b * G;
    float gi = sigmoidf_(g[d]);
    float gf = sigmoidf_(g[D + d]);
    float gg = tanhf(g[2 * D + d]);
    float go = sigmoidf_(g[3 * D + d]);
    float c  = d_cst[idx];
    float cn = gf * c + gi * gg;
    float hn = go * tanhf(cn);
    if (t < d_dlen[b]) { d_cst[idx] = cn; d_hst[idx] = hn; }
    d_Hbuf[(size_t)(b * T + t) * D + d] = hn;
}

// ---------------------------------------------------------------------------
extern "C" void kernel_launch(void* const* d_in, const int* in_sizes, int n_in,
                              void* d_out, int out_size)
{
    const float* feats  = (const float*)d_in[0];
    const int*   caps   = (const int*)  d_in[1];
    const int*   clen   = (const int*)  d_in[2];
    const float* emb    = (const float*)d_in[3];
    const float* att1_w = (const float*)d_in[4];
    const float* att1_b = (const float*)d_in[5];
    const float* w_ih   = (const float*)d_in[6];
    const float* w_hh   = (const float*)d_in[7];
    const float* b_ih   = (const float*)d_in[8];
    const float* b_hh   = (const float*)d_in[9];
    const float* word_w = (const float*)d_in[10];
    const float* word_b = (const float*)d_in[11];
    float* out = (float*)d_out;

    float *fm, *hst, *cst, *gates, *xproj, *Hbuf, *bias2;
    int *sortind, *dlen, *tok;
    cudaGetSymbolAddress((void**)&fm,      d_fm);
    cudaGetSymbolAddress((void**)&hst,     d_hst);
    cudaGetSymbolAddress((void**)&cst,     d_cst);
    cudaGetSymbolAddress((void**)&gates,   d_gates);
    cudaGetSymbolAddress((void**)&xproj,   d_xproj);
    cudaGetSymbolAddress((void**)&Hbuf,    d_Hbuf);
    cudaGetSymbolAddress((void**)&bias2,   d_bias2);
    cudaGetSymbolAddress((void**)&sortind, d_sortind);
    cudaGetSymbolAddress((void**)&dlen,    d_dlen);
    cudaGetSymbolAddress((void**)&tok,     d_tok);

    const long long PRED = (long long)NB * T * V;
    int write_tail = ((long long)out_size >= PRED + NB * L + 2 * NB) ? 1 : 0;

    // 1) sort + prep
    prep_kernel<<<1, NB>>>(clen, caps, b_ih, b_hh, out, write_tail);

    // 2) sorted mean features (reads the 205MB input once)
    mean_kernel<<<NB, 256>>>(feats);

    // 3) h0 = fm @ att1_w^T + att1_b   [128,512] K=2048
    gemm_tn<1><<<dim3(NB / 16, D / 64), 256>>>(
        fm, FEAT, nullptr, att1_w, att1_b, nullptr, 0, hst, D, D, FEAT, nullptr);

    // 4) input projection for ALL steps at once:
    //    xproj[r] = emb_table[tok[r]] @ w_ih^T + (b_ih + b_hh)   [6528,2048] K=512
    gemm_tn<4><<<dim3(R / 64, G / 64), 256>>>(
        emb, E, tok, w_ih, bias2, nullptr, 0, xproj, G, G, E, nullptr);

    // 5) sequential LSTM: per step only h @ w_hh^T remains
    for (int t = 0; t < T; t++) {
        gemm_tn<2><<<dim3(NB / 32, G / 64), 256>>>(
            hst, D, nullptr, w_hh, nullptr,
            xproj + (size_t)t * G, T * G,
            gates, G, G, D, nullptr);
        lstm_pointwise<<<NB * D / 256, 256>>>(t);
    }

    // 6) batched, masked word projection into d_out predictions
    //    pred[r] = valid ? Hbuf[r] @ word_w^T + word_b : 0
    gemm_tn<4><<<dim3(R / 64, (V + 63) / 64), 256>>>(
        Hbuf, D, nullptr, word_w, word_b, nullptr, 0, out, V, V, D, dlen);
}

// round 5
// speedup vs baseline: 2.0850x; 2.0850x over previous
#include <cuda_runtime.h>
#include <math.h>

constexpr int NB=128, NP=196, FEAT=2048, E=512, D=512, V=10000, L=52, T=51;
constexpr int G=2048, R=NB*T;

__device__ float d_fm[NB*FEAT];
__device__ float d_hA[NB*D];
__device__ float d_hB[NB*D];
__device__ float d_xproj[(size_t)R*G];
__device__ float d_Hbuf[(size_t)R*D];
__device__ int d_sortind[NB], d_dlen[NB], d_start[NB], d_nt[T];
__device__ int d_S;
__device__ int d_tok[R], d_vrow[R];
__device__ float d_bias2[G];
__device__ unsigned int d_ctr;   // grid-barrier counter, reset by prep each launch

__device__ __forceinline__ void fma2(unsigned long long &d,
                                     unsigned long long a, unsigned long long b){
    asm("fma.rn.f32x2 %0, %1, %2, %0;" : "+l"(d) : "l"(a), "l"(b));
}
__device__ __forceinline__ unsigned long long dup2(float v){
    unsigned long long r; asm("mov.b64 %0, {%1, %1};" : "=l"(r) : "f"(v)); return r;
}
__device__ __forceinline__ float2 unpk(unsigned long long v){
    float2 f; asm("mov.b64 {%0, %1}, %2;" : "=f"(f.x), "=f"(f.y) : "l"(v)); return f;
}

// ---------------------------------------------------------------------------
__global__ void prep_kernel(const int* __restrict__ clen,
                            const int* __restrict__ caps,
                            const float* __restrict__ b_ih,
                            const float* __restrict__ b_hh,
                            float* __restrict__ out, int write_tail)
{
    __shared__ int s_len[NB], s_dl[NB];
    int tid = threadIdx.x;
    if (tid == 0) d_ctr = 0u;             // reset grid barrier every launch
    s_len[tid] = clen[tid];
    __syncthreads();
    int li = s_len[tid], rank = 0;
    for (int j = 0; j < NB; j++) {
        int lj = s_len[j];
        rank += (lj > li) || (lj == li && j < tid);
    }
    d_sortind[rank] = tid;
    __syncthreads();
    int src = d_sortind[tid];
    int dl  = s_len[src] - 1;
    d_dlen[tid] = dl;
    s_dl[tid] = dl;
    for (int r = tid; r < R; r += NB) { d_vrow[r] = 0; d_tok[r] = 0; }
    __syncthreads();
    if (tid < T) {
        int c = 0;
        for (int b = 0; b < NB; b++) c += (s_dl[b] > tid);
        d_nt[tid] = c;
    }
    int st = 0;
    for (int j = 0; j < tid; j++) st += s_dl[j];
    d_start[tid] = st;
    if (tid == NB - 1) d_S = st + dl;
    for (int t = 0; t < dl; t++) {
        d_vrow[st + t] = tid * T + t;
        d_tok[st + t]  = caps[src * L + t];
    }
    if (write_tail) {
        float* out_caps = out + (size_t)NB * T * V;
        float* out_dlen = out_caps + (size_t)NB * L;
        float* out_sort = out_dlen + NB;
        out_dlen[tid] = (float)dl;
        out_sort[tid] = (float)src;
        for (int j = 0; j < L; j++)
            out_caps[tid * L + j] = (float)caps[src * L + j];
    }
    for (int j = tid; j < G; j += NB) d_bias2[j] = b_ih[j] + b_hh[j];
}

// ---------------------------------------------------------------------------
__global__ void mean_kernel(const float* __restrict__ feats)
{
    int b = blockIdx.x, src = d_sortind[b], tid = threadIdx.x;
    const float* base = feats + (size_t)src * NP * FEAT;
    float acc[FEAT / 256];
    #pragma unroll
    for (int j = 0; j < FEAT / 256; j++) acc[j] = 0.f;
    for (int p = 0; p < NP; p++) {
        const float* row = base + (size_t)p * FEAT;
        #pragma unroll
        for (int j = 0; j < FEAT / 256; j++) acc[j] += __ldg(&row[tid + j * 256]);
    }
    #pragma unroll
    for (int j = 0; j < FEAT / 256; j++)
        d_fm[b * FEAT + tid + j * 256] = acc[j] * (1.f / NP);
}

// ---------------------------------------------------------------------------
// h0 = fm @ att1_w^T + att1_b.  grid (NB, 4), 256 thr, warp-per-column.
// ---------------------------------------------------------------------------
__global__ void h0_kernel(const float* __restrict__ att1_w,
                          const float* __restrict__ att1_b)
{
    __shared__ float s_fm[FEAT];
    int b = blockIdx.x, c0 = blockIdx.y * 128;
    for (int i = threadIdx.x; i < FEAT; i += 256) s_fm[i] = d_fm[b * FEAT + i];
    __syncthreads();
    int warp = threadIdx.x >> 5, lane = threadIdx.x & 31;
    for (int cc = warp; cc < 128; cc += 8) {
        int col = c0 + cc;
        const float4* wr = (const float4*)(att1_w + (size_t)col * FEAT);
        float s = 0.f;
        for (int k = lane; k < FEAT / 4; k += 32) {
            float4 w = __ldg(&wr[k]);
            float4 f = *(const float4*)&s_fm[k * 4];
            s += w.x * f.x + w.y * f.y + w.z * f.z + w.w * f.w;
        }
        #pragma unroll
        for (int o = 16; o; o >>= 1) s += __shfl_down_sync(~0u, s, o);
        if (!lane) d_hA[b * D + col] = s + __ldg(&att1_b[col]);
    }
}

// ---------------------------------------------------------------------------
// 128x128x16 double-buffered fp32 GEMM with fma.rn.f32x2.
// C = A[M,K] @ B[N,K]^T + bias. Optional A gather (aIdx) and output row
// scatter (outIdx) with valid-row limit *MvP.
// ---------------------------------------------------------------------------
template<bool GA, bool SCAT>
__global__ __launch_bounds__(256, 2) void gemm128(
    const float* __restrict__ A, int lda, const int* __restrict__ aIdx,
    const float* __restrict__ Bm, const float* __restrict__ bias,
    float* __restrict__ Cout, int ldc, const int* __restrict__ outIdx,
    const int* __restrict__ MvP, int N, int K)
{
    __shared__ __align__(16) float As[2][16][132];
    __shared__ __align__(16) float Bs[2][16][132];
    __shared__ int s_src[128];

    int m0 = blockIdx.x * 128, n0 = blockIdx.y * 128;
    int Mv = MvP ? __ldg(MvP) : 0x7fffffff;
    if (m0 >= Mv) return;

    int tid = threadIdx.x;
    if (tid < 128) s_src[tid] = GA ? __ldg(&aIdx[m0 + tid]) : (m0 + tid);
    __syncthreads();

    int tx = tid & 15, ty = tid >> 4;
    int tx4 = tx * 4, ty4 = ty * 4;
    int j1 = tid + 256;
    int r0 = tid >> 2, q0 = tid & 3;
    int r1 = j1 >> 2,  q1 = j1 & 3;
    const float* Ar0 = A + (size_t)s_src[r0] * lda + q0 * 4;
    const float* Ar1 = A + (size_t)s_src[r1] * lda + q1 * 4;
    bool bok0 = (n0 + r0) < N, bok1 = (n0 + r1) < N;
    const float* Br0 = Bm + (size_t)(n0 + r0) * K + q0 * 4;
    const float* Br1 = Bm + (size_t)(n0 + r1) * K + q1 * 4;
    const float4 z4 = make_float4(0.f, 0.f, 0.f, 0.f);

    unsigned long long acc[4][8];
    #pragma unroll
    for (int p = 0; p < 4; p++)
        #pragma unroll
        for (int j = 0; j < 8; j++) acc[p][j] = 0ull;

    float4 ra0 = __ldg((const float4*)Ar0);
    float4 ra1 = __ldg((const float4*)Ar1);
    float4 rb0 = bok0 ? __ldg((const float4*)Br0) : z4;
    float4 rb1 = bok1 ? __ldg((const float4*)Br1) : z4;
    As[0][q0*4+0][r0]=ra0.x; As[0][q0*4+1][r0]=ra0.y; As[0][q0*4+2][r0]=ra0.z; As[0][q0*4+3][r0]=ra0.w;
    As[0][q1*4+0][r1]=ra1.x; As[0][q1*4+1][r1]=ra1.y; As[0][q1*4+2][r1]=ra1.z; As[0][q1*4+3][r1]=ra1.w;
    Bs[0][q0*4+0][r0]=rb0.x; Bs[0][q0*4+1][r0]=rb0.y; Bs[0][q0*4+2][r0]=rb0.z; Bs[0][q0*4+3][r0]=rb0.w;
    Bs[0][q1*4+0][r1]=rb1.x; Bs[0][q1*4+1][r1]=rb1.y; Bs[0][q1*4+2][r1]=rb1.z; Bs[0][q1*4+3][r1]=rb1.w;
    __syncthreads();

    const int KT = K / 16;
    for (int kt = 0; kt < KT; kt++) {
        int cur = kt & 1;
        if (kt + 1 < KT) {
            int ko = (kt + 1) * 16;
            ra0 = __ldg((const float4*)(Ar0 + ko));
            ra1 = __ldg((const float4*)(Ar1 + ko));
            rb0 = bok0 ? __ldg((const float4*)(Br0 + ko)) : z4;
            rb1 = bok1 ? __ldg((const float4*)(Br1 + ko)) : z4;
        }
        #pragma unroll
        for (int k = 0; k < 16; k++) {
            ulonglong2 a01 = *(const ulonglong2*)&As[cur][k][ty4];
            ulonglong2 a23 = *(const ulonglong2*)&As[cur][k][ty4 + 64];
            float4 b0 = *(const float4*)&Bs[cur][k][tx4];
            float4 b1 = *(const float4*)&Bs[cur][k][tx4 + 64];
            unsigned long long pa[4] = {a01.x, a01.y, a23.x, a23.y};
            unsigned long long pb[8] = {dup2(b0.x), dup2(b0.y), dup2(b0.z), dup2(b0.w),
                                        dup2(b1.x), dup2(b1.y), dup2(b1.z), dup2(b1.w)};
            #pragma unroll
            for (int p = 0; p < 4; p++)
                #pragma unroll
                for (int j = 0; j < 8; j++)
                    fma2(acc[p][j], pa[p], pb[j]);
        }
        if (kt + 1 < KT) {
            int nb = 1 - cur;
            As[nb][q0*4+0][r0]=ra0.x; As[nb][q0*4+1][r0]=ra0.y; As[nb][q0*4+2][r0]=ra0.z; As[nb][q0*4+3][r0]=ra0.w;
            As[nb][q1*4+0][r1]=ra1.x; As[nb][q1*4+1][r1]=ra1.y; As[nb][q1*4+2][r1]=ra1.z; As[nb][q1*4+3][r1]=ra1.w;
            Bs[nb][q0*4+0][r0]=rb0.x; Bs[nb][q0*4+1][r0]=rb0.y; Bs[nb][q0*4+2][r0]=rb0.z; Bs[nb][q0*4+3][r0]=rb0.w;
            Bs[nb][q1*4+0][r1]=rb1.x; Bs[nb][q1*4+1][r1]=rb1.y; Bs[nb][q1*4+2][r1]=rb1.z; Bs[nb][q1*4+3][r1]=rb1.w;
        }
        __syncthreads();
    }

    bool cok0 = (n0 + tx4) < N, cok1 = (n0 + tx4 + 64) < N;
    float4 bi0 = z4, bi1 = z4;
    if (bias) {
        if (cok0) bi0 = __ldg((const float4*)(bias + n0 + tx4));
        if (cok1) bi1 = __ldg((const float4*)(bias + n0 + tx4 + 64));
    }
    #pragma unroll
    for (int p = 0; p < 4; p++) {
        int rbase = m0 + ((p < 2) ? (ty4 + 2 * p) : (64 + ty4 + 2 * (p - 2)));
        float2 u[8];
        #pragma unroll
        for (int j = 0; j < 8; j++) u[j] = unpk(acc[p][j]);
        float4 lo0 = make_float4(u[0].x+bi0.x, u[1].x+bi0.y, u[2].x+bi0.z, u[3].x+bi0.w);
        float4 lo1 = make_float4(u[4].x+bi1.x, u[5].x+bi1.y, u[6].x+bi1.z, u[7].x+bi1.w);
        float4 hi0 = make_float4(u[0].y+bi0.x, u[1].y+bi0.y, u[2].y+bi0.z, u[3].y+bi0.w);
        float4 hi1 = make_float4(u[4].y+bi1.x, u[5].y+bi1.y, u[6].y+bi1.z, u[7].y+bi1.w);
        if (!SCAT || rbase < Mv) {
            size_t orow = SCAT ? (size_t)__ldg(&outIdx[rbase]) : (size_t)rbase;
            if (cok0) *(float4*)(Cout + orow * ldc + n0 + tx4)      = lo0;
            if (cok1) *(float4*)(Cout + orow * ldc + n0 + tx4 + 64) = lo1;
        }
        int rh = rbase + 1;
        if (!SCAT || rh < Mv) {
            size_t orow = SCAT ? (size_t)__ldg(&outIdx[rh]) : (size_t)rh;
            if (cok0) *(float4*)(Cout + orow * ldc + n0 + tx4)      = hi0;
            if (cok1) *(float4*)(Cout + orow * ldc + n0 + tx4 + 64) = hi1;
        }
    }
}

// ---------------------------------------------------------------------------
__global__ void zerofill(float* __restrict__ out)
{
    int r = blockIdx.x, b = r / T, t = r - b * T;
    if (t < d_dlen[b]) return;
    float4* p = (float4*)(out + (size_t)r * V);
    float4 z = make_float4(0.f, 0.f, 0.f, 0.f);
    for (int i = threadIdx.x; i < V / 4; i += blockDim.x) p[i] = z;
}

// ---------------------------------------------------------------------------
// persistent LSTM: 128 blocks, block j owns d-cols 4j..4j+3 of each gate.
// Grid barrier: monotonically increasing atomic counter, reset by prep.
// ---------------------------------------------------------------------------
__global__ __launch_bounds__(256) void lstm_persist(const float* __restrict__ w_hh)
{
    __shared__ float w_s[512][16];
    __shared__ __align__(16) float hs[16][132];
    __shared__ float c_s[512];
    __shared__ int s_start[NB];
    __shared__ int s_nt[T];

    int tid = threadIdx.x, d0 = blockIdx.x * 4;
    int tx = tid & 15, ty = tid >> 4;

    #pragma unroll
    for (int s = 0; s < 8; s++) {
        int lin = tid + s * 256;
        int i = lin >> 7, q = lin & 127;
        int gc = (i >> 2) * 512 + d0 + (i & 3);
        float4 v = __ldg((const float4*)(w_hh + (size_t)gc * 512 + q * 4));
        w_s[q*4+0][i]=v.x; w_s[q*4+1][i]=v.y; w_s[q*4+2][i]=v.z; w_s[q*4+3][i]=v.w;
    }
    if (tid < NB) s_start[tid] = d_start[tid];
    if (tid < T)  s_nt[tid] = d_nt[tid];
    for (int e = tid; e < 512; e += 256) c_s[e] = 0.f;
    __syncthreads();

    for (int t = 0; t < T; t++) {
        int nt = s_nt[t];
        int nt8 = (nt + 7) & ~7;
        bool rowok = (ty * 8) < nt8;
        const float* hc = (t & 1) ? d_hB : d_hA;
        float*       hw = (t & 1) ? d_hA : d_hB;

        unsigned long long acc[4] = {0ull, 0ull, 0ull, 0ull};
        for (int kc = 0; kc < 32; kc++) {
            #pragma unroll
            for (int s = 0; s < 2; s++) {
                int lin = tid + s * 256;
                int row = lin >> 2, q = lin & 3;
                if (row < nt8) {
                    float4 v = __ldcg((const float4*)(hc + (size_t)row * 512 + kc * 16 + q * 4));
                    hs[q*4+0][row]=v.x; hs[q*4+1][row]=v.y; hs[q*4+2][row]=v.z; hs[q*4+3][row]=v.w;
                }
            }
            __syncthreads();
            if (rowok) {
                #pragma unroll
                for (int k = 0; k < 16; k++) {
                    ulonglong2 h01 = *(const ulonglong2*)&hs[k][ty * 8];
                    ulonglong2 h23 = *(const ulonglong2*)&hs[k][ty * 8 + 4];
                    unsigned long long wd = dup2(w_s[kc * 16 + k][tx]);
                    fma2(acc[0], h01.x, wd);
                    fma2(acc[1], h01.y, wd);
                    fma2(acc[2], h23.x, wd);
                    fma2(acc[3], h23.y, wd);
                }
            }
            __syncthreads();
        }
        #pragma unroll
        for (int p = 0; p < 4; p++) {
            float2 f = unpk(acc[p]);
            hs[tx][ty * 8 + p * 2 + 0] = f.x;
            hs[tx][ty * 8 + p * 2 + 1] = f.y;
        }
        __syncthreads();
        for (int e = tid; e < 512; e += 256) {
            int b = e >> 2, dd = e & 3;
            if (b < nt) {
                size_t cidx = (size_t)(s_start[b] + t);
                const float* xp = d_xproj + cidx * G + d0 + dd;
                float g0 = hs[dd][b]      + __ldg(xp);
                float g1 = hs[4 + dd][b]  + __ldg(xp + 512);
                float g2 = hs[8 + dd][b]  + __ldg(xp + 1024);
                float g3 = hs[12 + dd][b] + __ldg(xp + 1536);
                float gi = 1.f / (1.f + __expf(-g0));
                float gf = 1.f / (1.f + __expf(-g1));
                float gg = tanhf(g2);
                float go = 1.f / (1.f + __expf(-g3));
                float c  = c_s[e];
                float cn = gf * c + gi * gg;
                float hn = go * tanhf(cn);
                c_s[e] = cn;
                __stcg(hw + (size_t)b * 512 + d0 + dd, hn);
                d_Hbuf[cidx * 512 + d0 + dd] = hn;
            }
        }
        // ---- grid barrier (monotone counter; reset to 0 by prep_kernel) ----
        if (t < T - 1) {
            unsigned int target = (unsigned int)(t + 1) * (unsigned int)gridDim.x;
            __syncthreads();
            if (tid == 0) {
                __threadfence();                       // release our writes
                atomicAdd(&d_ctr, 1u);
                while (*(volatile unsigned int*)&d_ctr < target) __nanosleep(64);
                __threadfence();                       // acquire others' writes
            }
            __syncthreads();
        }
    }
}

// ---------------------------------------------------------------------------
extern "C" void kernel_launch(void* const* d_in, const int* in_sizes, int n_in,
                              void* d_out, int out_size)
{
    const float* feats  = (const float*)d_in[0];
    const int*   caps   = (const int*)  d_in[1];
    const int*   clen   = (const int*)  d_in[2];
    const float* emb    = (const float*)d_in[3];
    const float* att1_w = (const float*)d_in[4];
    const float* att1_b = (const float*)d_in[5];
    const float* w_ih   = (const float*)d_in[6];
    const float* w_hh   = (const float*)d_in[7];
    const float* b_ih   = (const float*)d_in[8];
    const float* b_hh   = (const float*)d_in[9];
    const float* word_w = (const float*)d_in[10];
    const float* word_b = (const float*)d_in[11];
    float* out = (float*)d_out;

    float *xproj, *Hbuf, *bias2;
    int *tok, *vrow, *Sp;
    cudaGetSymbolAddress((void**)&xproj, d_xproj);
    cudaGetSymbolAddress((void**)&Hbuf,  d_Hbuf);
    cudaGetSymbolAddress((void**)&bias2, d_bias2);
    cudaGetSymbolAddress((void**)&tok,   d_tok);
    cudaGetSymbolAddress((void**)&vrow,  d_vrow);
    cudaGetSymbolAddress((void**)&Sp,    d_S);

    const long long PRED = (long long)NB * T * V;
    int write_tail = ((long long)out_size >= PRED + NB * L + 2 * NB) ? 1 : 0;

    prep_kernel<<<1, NB>>>(clen, caps, b_ih, b_hh, out, write_tail);
    mean_kernel<<<NB, 256>>>(feats);
    h0_kernel<<<dim3(NB, 4), 256>>>(att1_w, att1_b);

    // xproj (compacted rows): emb[tok] @ w_ih^T + (b_ih+b_hh)
    gemm128<true, false><<<dim3(R / 128, G / 128), 256>>>(
        emb, E, tok, w_ih, bias2, xproj, G, nullptr, Sp, G, E);

    zerofill<<<R, 256>>>(out);

    lstm_persist<<<NB, 256>>>(w_hh);

    // word projection (compacted rows, scatter to out)
    gemm128<false, true><<<dim3(R / 128, (V + 127) / 128), 256>>>(
        Hbuf, D, nullptr, word_w, word_b, out, V, vrow, Sp, V, D);
}

// round 7
// speedup vs baseline: 2.1377x; 1.0253x over previous
#include <cuda_runtime.h>
#include <math.h>

constexpr int NB=128, NP=196, FEAT=2048, E=512, D=512, V=10000, L=52, T=51;
constexpr int G=2048, R=NB*T;

__device__ float d_fm[NB*FEAT];
__device__ float d_hA[NB*D];
__device__ float d_hB[NB*D];
__device__ float d_xproj[(size_t)R*G];
__device__ float d_Hbuf[(size_t)R*D];
__device__ int d_sortind[NB], d_dlen[NB], d_start[NB], d_nt[T];
__device__ int d_S;
__device__ int d_tok[R], d_vrow[R];
__device__ float d_bias2[G];
__device__ unsigned int d_ctr;   // grid-barrier counter, reset by prep each launch

__device__ __forceinline__ void fma2(unsigned long long &d,
                                     unsigned long long a, unsigned long long b){
    asm("fma.rn.f32x2 %0, %1, %2, %0;" : "+l"(d) : "l"(a), "l"(b));
}
__device__ __forceinline__ unsigned long long dup2(float v){
    unsigned long long r; asm("mov.b64 %0, {%1, %1};" : "=l"(r) : "f"(v)); return r;
}
__device__ __forceinline__ float2 unpk(unsigned long long v){
    float2 f; asm("mov.b64 {%0, %1}, %2;" : "=f"(f.x), "=f"(f.y) : "l"(v)); return f;
}
__device__ __forceinline__ unsigned tf32_of(float f){
    unsigned u; asm("cvt.rna.tf32.f32 %0, %1;" : "=r"(u) : "f"(f)); return u;
}
__device__ __forceinline__ void mma_tf32(float* c, const unsigned* a, const unsigned* b){
    asm("mma.sync.aligned.m16n8k8.row.col.f32.tf32.tf32.f32 "
        "{%0,%1,%2,%3}, {%4,%5,%6,%7}, {%8,%9}, {%0,%1,%2,%3};"
        : "+f"(c[0]),"+f"(c[1]),"+f"(c[2]),"+f"(c[3])
        : "r"(a[0]),"r"(a[1]),"r"(a[2]),"r"(a[3]),"r"(b[0]),"r"(b[1]));
}

// ---------------------------------------------------------------------------
__global__ void prep_kernel(const int* __restrict__ clen,
                            const int* __restrict__ caps,
                            const float* __restrict__ b_ih,
                            const float* __restrict__ b_hh,
                            float* __restrict__ out, int write_tail)
{
    __shared__ int s_len[NB], s_dl[NB];
    int tid = threadIdx.x;
    if (tid == 0) d_ctr = 0u;
    s_len[tid] = clen[tid];
    __syncthreads();
    int li = s_len[tid], rank = 0;
    for (int j = 0; j < NB; j++) {
        int lj = s_len[j];
        rank += (lj > li) || (lj == li && j < tid);
    }
    d_sortind[rank] = tid;
    __syncthreads();
    int src = d_sortind[tid];
    int dl  = s_len[src] - 1;
    d_dlen[tid] = dl;
    s_dl[tid] = dl;
    for (int r = tid; r < R; r += NB) { d_vrow[r] = 0; d_tok[r] = 0; }
    __syncthreads();
    if (tid < T) {
        int c = 0;
        for (int b = 0; b < NB; b++) c += (s_dl[b] > tid);
        d_nt[tid] = c;
    }
    int st = 0;
    for (int j = 0; j < tid; j++) st += s_dl[j];
    d_start[tid] = st;
    if (tid == NB - 1) d_S = st + dl;
    for (int t = 0; t < dl; t++) {
        d_vrow[st + t] = tid * T + t;
        d_tok[st + t]  = caps[src * L + t];
    }
    if (write_tail) {
        float* out_caps = out + (size_t)NB * T * V;
        float* out_dlen = out_caps + (size_t)NB * L;
        float* out_sort = out_dlen + NB;
        out_dlen[tid] = (float)dl;
        out_sort[tid] = (float)src;
        for (int j = 0; j < L; j++)
            out_caps[tid * L + j] = (float)caps[src * L + j];
    }
    for (int j = tid; j < G; j += NB) d_bias2[j] = b_ih[j] + b_hh[j];
}

// ---------------------------------------------------------------------------
__global__ void mean_kernel(const float* __restrict__ feats)
{
    int b = blockIdx.x, src = d_sortind[b], tid = threadIdx.x;
    const float* base = feats + (size_t)src * NP * FEAT;
    float acc[FEAT / 256];
    #pragma unroll
    for (int j = 0; j < FEAT / 256; j++) acc[j] = 0.f;
    for (int p = 0; p < NP; p++) {
        const float* row = base + (size_t)p * FEAT;
        #pragma unroll
        for (int j = 0; j < FEAT / 256; j++) acc[j] += __ldg(&row[tid + j * 256]);
    }
    #pragma unroll
    for (int j = 0; j < FEAT / 256; j++)
        d_fm[b * FEAT + tid + j * 256] = acc[j] * (1.f / NP);
}

// ---------------------------------------------------------------------------
__global__ void h0_kernel(const float* __restrict__ att1_w,
                          const float* __restrict__ att1_b)
{
    __shared__ float s_fm[FEAT];
    int b = blockIdx.x, c0 = blockIdx.y * 128;
    for (int i = threadIdx.x; i < FEAT; i += 256) s_fm[i] = d_fm[b * FEAT + i];
    __syncthreads();
    int warp = threadIdx.x >> 5, lane = threadIdx.x & 31;
    for (int cc = warp; cc < 128; cc += 8) {
        int col = c0 + cc;
        const float4* wr = (const float4*)(att1_w + (size_t)col * FEAT);
        float s = 0.f;
        for (int k = lane; k < FEAT / 4; k += 32) {
            float4 w = __ldg(&wr[k]);
            float4 f = *(const float4*)&s_fm[k * 4];
            s += w.x * f.x + w.y * f.y + w.z * f.z + w.w * f.w;
        }
        #pragma unroll
        for (int o = 16; o; o >>= 1) s += __shfl_down_sync(~0u, s, o);
        if (!lane) d_hA[b * D + col] = s + __ldg(&att1_b[col]);
    }
}

// ---------------------------------------------------------------------------
// fp32 f32x2 GEMM (used for xproj). Proven in round 5.
// ---------------------------------------------------------------------------
template<bool GA, bool SCAT>
__global__ __launch_bounds__(256, 2) void gemm128(
    const float* __restrict__ A, int lda, const int* __restrict__ aIdx,
    const float* __restrict__ Bm, const float* __restrict__ bias,
    float* __restrict__ Cout, int ldc, const int* __restrict__ outIdx,
    const int* __restrict__ MvP, int N, int K)
{
    __shared__ __align__(16) float As[2][16][132];
    __shared__ __align__(16) float Bs[2][16][132];
    __shared__ int s_src[128];

    int m0 = blockIdx.x * 128, n0 = blockIdx.y * 128;
    int Mv = MvP ? __ldg(MvP) : 0x7fffffff;
    if (m0 >= Mv) return;

    int tid = threadIdx.x;
    if (tid < 128) s_src[tid] = GA ? __ldg(&aIdx[m0 + tid]) : (m0 + tid);
    __syncthreads();

    int tx = tid & 15, ty = tid >> 4;
    int tx4 = tx * 4, ty4 = ty * 4;
    int j1 = tid + 256;
    int r0 = tid >> 2, q0 = tid & 3;
    int r1 = j1 >> 2,  q1 = j1 & 3;
    const float* Ar0 = A + (size_t)s_src[r0] * lda + q0 * 4;
    const float* Ar1 = A + (size_t)s_src[r1] * lda + q1 * 4;
    bool bok0 = (n0 + r0) < N, bok1 = (n0 + r1) < N;
    const float* Br0 = Bm + (size_t)(n0 + r0) * K + q0 * 4;
    const float* Br1 = Bm + (size_t)(n0 + r1) * K + q1 * 4;
    const float4 z4 = make_float4(0.f, 0.f, 0.f, 0.f);

    unsigned long long acc[4][8];
    #pragma unroll
    for (int p = 0; p < 4; p++)
        #pragma unroll
        for (int j = 0; j < 8; j++) acc[p][j] = 0ull;

    float4 ra0 = __ldg((const float4*)Ar0);
    float4 ra1 = __ldg((const float4*)Ar1);
    float4 rb0 = bok0 ? __ldg((const float4*)Br0) : z4;
    float4 rb1 = bok1 ? __ldg((const float4*)Br1) : z4;
    As[0][q0*4+0][r0]=ra0.x; As[0][q0*4+1][r0]=ra0.y; As[0][q0*4+2][r0]=ra0.z; As[0][q0*4+3][r0]=ra0.w;
    As[0][q1*4+0][r1]=ra1.x; As[0][q1*4+1][r1]=ra1.y; As[0][q1*4+2][r1]=ra1.z; As[0][q1*4+3][r1]=ra1.w;
    Bs[0][q0*4+0][r0]=rb0.x; Bs[0][q0*4+1][r0]=rb0.y; Bs[0][q0*4+2][r0]=rb0.z; Bs[0][q0*4+3][r0]=rb0.w;
    Bs[0][q1*4+0][r1]=rb1.x; Bs[0][q1*4+1][r1]=rb1.y; Bs[0][q1*4+2][r1]=rb1.z; Bs[0][q1*4+3][r1]=rb1.w;
    __syncthreads();

    const int KT = K / 16;
    for (int kt = 0; kt < KT; kt++) {
        int cur = kt & 1;
        if (kt + 1 < KT) {
            int ko = (kt + 1) * 16;
            ra0 = __ldg((const float4*)(Ar0 + ko));
            ra1 = __ldg((const float4*)(Ar1 + ko));
            rb0 = bok0 ? __ldg((const float4*)(Br0 + ko)) : z4;
            rb1 = bok1 ? __ldg((const float4*)(Br1 + ko)) : z4;
        }
        #pragma unroll
        for (int k = 0; k < 16; k++) {
            ulonglong2 a01 = *(const ulonglong2*)&As[cur][k][ty4];
            ulonglong2 a23 = *(const ulonglong2*)&As[cur][k][ty4 + 64];
            float4 b0 = *(const float4*)&Bs[cur][k][tx4];
            float4 b1 = *(const float4*)&Bs[cur][k][tx4 + 64];
            unsigned long long pa[4] = {a01.x, a01.y, a23.x, a23.y};
            unsigned long long pb[8] = {dup2(b0.x), dup2(b0.y), dup2(b0.z), dup2(b0.w),
                                        dup2(b1.x), dup2(b1.y), dup2(b1.z), dup2(b1.w)};
            #pragma unroll
            for (int p = 0; p < 4; p++)
                #pragma unroll
                for (int j = 0; j < 8; j++)
                    fma2(acc[p][j], pa[p], pb[j]);
        }
        if (kt + 1 < KT) {
            int nb = 1 - cur;
            As[nb][q0*4+0][r0]=ra0.x; As[nb][q0*4+1][r0]=ra0.y; As[nb][q0*4+2][r0]=ra0.z; As[nb][q0*4+3][r0]=ra0.w;
            As[nb][q1*4+0][r1]=ra1.x; As[nb][q1*4+1][r1]=ra1.y; As[nb][q1*4+2][r1]=ra1.z; As[nb][q1*4+3][r1]=ra1.w;
            Bs[nb][q0*4+0][r0]=rb0.x; Bs[nb][q0*4+1][r0]=rb0.y; Bs[nb][q0*4+2][r0]=rb0.z; Bs[nb][q0*4+3][r0]=rb0.w;
            Bs[nb][q1*4+0][r1]=rb1.x; Bs[nb][q1*4+1][r1]=rb1.y; Bs[nb][q1*4+2][r1]=rb1.z; Bs[nb][q1*4+3][r1]=rb1.w;
        }
        __syncthreads();
    }

    bool cok0 = (n0 + tx4) < N, cok1 = (n0 + tx4 + 64) < N;
    float4 bi0 = z4, bi1 = z4;
    if (bias) {
        if (cok0) bi0 = __ldg((const float4*)(bias + n0 + tx4));
        if (cok1) bi1 = __ldg((const float4*)(bias + n0 + tx4 + 64));
    }
    #pragma unroll
    for (int p = 0; p < 4; p++) {
        int rbase = m0 + ((p < 2) ? (ty4 + 2 * p) : (64 + ty4 + 2 * (p - 2)));
        float2 u[8];
        #pragma unroll
        for (int j = 0; j < 8; j++) u[j] = unpk(acc[p][j]);
        float4 lo0 = make_float4(u[0].x+bi0.x, u[1].x+bi0.y, u[2].x+bi0.z, u[3].x+bi0.w);
        float4 lo1 = make_float4(u[4].x+bi1.x, u[5].x+bi1.y, u[6].x+bi1.z, u[7].x+bi1.w);
        float4 hi0 = make_float4(u[0].y+bi0.x, u[1].y+bi0.y, u[2].y+bi0.z, u[3].y+bi0.w);
        float4 hi1 = make_float4(u[4].y+bi1.x, u[5].y+bi1.y, u[6].y+bi1.z, u[7].y+bi1.w);
        if (!SCAT || rbase < Mv) {
            size_t orow = SCAT ? (size_t)__ldg(&outIdx[rbase]) : (size_t)rbase;
            if (cok0) *(float4*)(Cout + orow * ldc + n0 + tx4)      = lo0;
            if (cok1) *(float4*)(Cout + orow * ldc + n0 + tx4 + 64) = lo1;
        }
        int rh = rbase + 1;
        if (!SCAT || rh < Mv) {
            size_t orow = SCAT ? (size_t)__ldg(&outIdx[rh]) : (size_t)rh;
            if (cok0) *(float4*)(Cout + orow * ldc + n0 + tx4)      = hi0;
            if (cok1) *(float4*)(Cout + orow * ldc + n0 + tx4 + 64) = hi1;
        }
    }
}

// ---------------------------------------------------------------------------
// tf32 tensor-core word projection. 64x64x32 tiles, 8 warps (2m x 4n),
// 32KB static smem, fragment-layout smem (conflict-free vector LDS).
//   As: [mt<4][ks<4][lane<32][reg<4]   Bs: [nt<8][ks<4][lane<32][reg<2]
// ---------------------------------------------------------------------------
__global__ __launch_bounds__(256) void word_mma(
    const float* __restrict__ A,       // Hbuf [R][512]
    const float* __restrict__ Bm,      // word_w [V][512]
    const float* __restrict__ bias,    // word_b [V]
    float* __restrict__ Cout,          // out [R][V]
    const int* __restrict__ outIdx,    // vrow
    const int* __restrict__ MvP)       // d_S
{
    __shared__ unsigned As[2][2048];
    __shared__ unsigned Bs[2][2048];

    int m0 = blockIdx.x * 64, n0 = blockIdx.y * 64;
    int Mv = __ldg(MvP);
    if (m0 >= Mv) return;

    int tid = threadIdx.x, lane = tid & 31, w = tid >> 5;
    int wm = w & 1, wn = w >> 1;          // 2 x 4 warp grid
    int lrow = tid >> 3, q = tid & 7;     // each thread: 2 A rows + 2 B rows, 1 float4 each
    int ks_st = q >> 1;
    const float4 z4 = make_float4(0.f, 0.f, 0.f, 0.f);

    const float4* Ag0 = (const float4*)(A + (size_t)(m0 + lrow)      * D) + q;
    const float4* Ag1 = (const float4*)(A + (size_t)(m0 + lrow + 32) * D) + q;
    int br0 = n0 + lrow, br1 = n0 + lrow + 32;
    bool bok0 = br0 < V, bok1 = br1 < V;
    const float4* Bg0 = (const float4*)(Bm + (size_t)(bok0 ? br0 : 0) * D) + q;
    const float4* Bg1 = (const float4*)(Bm + (size_t)(bok1 ? br1 : 0) * D) + q;

    // smem store offsets (plain ints)
    int aoff0, aoff1, boff0, boff1;
    {
        int row = lrow, mt = row >> 4, r = row & 15;
        aoff0 = ((mt * 4 + ks_st) * 32 + (r & 7) * 4) * 4 + (r >> 3) + ((q & 1) << 1);
        row = lrow + 32; mt = row >> 4; r = row & 15;
        aoff1 = ((mt * 4 + ks_st) * 32 + (r & 7) * 4) * 4 + (r >> 3) + ((q & 1) << 1);
        row = lrow;      int nt = row >> 3, n = row & 7;
        boff0 = ((nt * 4 + ks_st) * 32 + n * 4) * 2 + (q & 1);
        row = lrow + 32; nt = row >> 3; n = row & 7;
        boff1 = ((nt * 4 + ks_st) * 32 + n * 4) * 2 + (q & 1);
    }

    float acc[2][2][4];
    #pragma unroll
    for (int i = 0; i < 2; i++)
        #pragma unroll
        for (int j = 0; j < 2; j++)
            #pragma unroll
            for (int r = 0; r < 4; r++) acc[i][j][r] = 0.f;

    float4 pa0 = __ldg(Ag0), pa1 = __ldg(Ag1);
    float4 pb0 = bok0 ? __ldg(Bg0) : z4;
    float4 pb1 = bok1 ? __ldg(Bg1) : z4;
    {
        unsigned* a = As[0];
        a[aoff0+0]=tf32_of(pa0.x); a[aoff0+4]=tf32_of(pa0.y); a[aoff0+8]=tf32_of(pa0.z); a[aoff0+12]=tf32_of(pa0.w);
        a[aoff1+0]=tf32_of(pa1.x); a[aoff1+4]=tf32_of(pa1.y); a[aoff1+8]=tf32_of(pa1.z); a[aoff1+12]=tf32_of(pa1.w);
        unsigned* bm = Bs[0];
        bm[boff0+0]=tf32_of(pb0.x); bm[boff0+2]=tf32_of(pb0.y); bm[boff0+4]=tf32_of(pb0.z); bm[boff0+6]=tf32_of(pb0.w);
        bm[boff1+0]=tf32_of(pb1.x); bm[boff1+2]=tf32_of(pb1.y); bm[boff1+4]=tf32_of(pb1.z); bm[boff1+6]=tf32_of(pb1.w);
    }
    __syncthreads();

    const int KT = D / 32;   // 16
    for (int kt = 0; kt < KT; kt++) {
        int cur = kt & 1;
        if (kt + 1 < KT) {
            int ko = (kt + 1) * 8;
            pa0 = __ldg(Ag0 + ko); pa1 = __ldg(Ag1 + ko);
            pb0 = bok0 ? __ldg(Bg0 + ko) : z4;
            pb1 = bok1 ? __ldg(Bg1 + ko) : z4;
        }
        #pragma unroll
        for (int ks = 0; ks < 4; ks++) {
            unsigned af[2][4], bf[2][2];
            #pragma unroll
            for (int i = 0; i < 2; i++)
                *(uint4*)af[i] = *(const uint4*)&As[cur][(((wm*2+i)*4 + ks)*32 + lane)*4];
            #pragma unroll
            for (int j = 0; j < 2; j++)
                *(uint2*)bf[j] = *(const uint2*)&Bs[cur][(((wn*2+j)*4 + ks)*32 + lane)*2];
            #pragma unroll
            for (int i = 0; i < 2; i++)
                #pragma unroll
                for (int j = 0; j < 2; j++)
                    mma_tf32(acc[i][j], af[i], bf[j]);
        }
        if (kt + 1 < KT) {
            int nb = 1 - cur;
            unsigned* a = As[nb];
            a[aoff0+0]=tf32_of(pa0.x); a[aoff0+4]=tf32_of(pa0.y); a[aoff0+8]=tf32_of(pa0.z); a[aoff0+12]=tf32_of(pa0.w);
            a[aoff1+0]=tf32_of(pa1.x); a[aoff1+4]=tf32_of(pa1.y); a[aoff1+8]=tf32_of(pa1.z); a[aoff1+12]=tf32_of(pa1.w);
            unsigned* bm = Bs[nb];
            bm[boff0+0]=tf32_of(pb0.x); bm[boff0+2]=tf32_of(pb0.y); bm[boff0+4]=tf32_of(pb0.z); bm[boff0+6]=tf32_of(pb0.w);
            bm[boff1+0]=tf32_of(pb1.x); bm[boff1+2]=tf32_of(pb1.y); bm[boff1+4]=tf32_of(pb1.z); bm[boff1+6]=tf32_of(pb1.w);
        }
        __syncthreads();
    }

    int r0 = lane >> 2, tg = lane & 3;
    #pragma unroll
    for (int i = 0; i < 2; i++) {
        int mloc = (wm * 2 + i) * 16 + r0;
        #pragma unroll
        for (int h = 0; h < 2; h++) {
            int gr = m0 + mloc + h * 8;
            if (gr < Mv) {
                size_t orow = (size_t)__ldg(&outIdx[gr]);
                float* outr = Cout + orow * V;
                #pragma unroll
                for (int j = 0; j < 2; j++) {
                    int gc = n0 + (wn * 2 + j) * 8 + tg * 2;
                    if (gc < V) {
                        float b0 = __ldg(&bias[gc]), b1 = __ldg(&bias[gc + 1]);
                        float2 v;
                        v.x = acc[i][j][h * 2 + 0] + b0;
                        v.y = acc[i][j][h * 2 + 1] + b1;
                        *(float2*)(outr + gc) = v;
                    }
                }
            }
        }
    }
}

// ---------------------------------------------------------------------------
__global__ void zerofill(float* __restrict__ out)
{
    int r = blockIdx.x, b = r / T, t = r - b * T;
    if (t < d_dlen[b]) return;
    float4* p = (float4*)(out + (size_t)r * V);
    float4 z = make_float4(0.f, 0.f, 0.f, 0.f);
    for (int i = threadIdx.x; i < V / 4; i += blockDim.x) p[i] = z;
}

// ---------------------------------------------------------------------------
// persistent LSTM (proven in round 5)
// ---------------------------------------------------------------------------
__global__ __launch_bounds__(256) void lstm_persist(const float* __restrict__ w_hh)
{
    __shared__ float w_s[512][16];
    __shared__ __align__(16) float hs[16][132];
    __shared__ float c_s[512];
    __shared__ int s_start[NB];
    __shared__ int s_nt[T];

    int tid = threadIdx.x, d0 = blockIdx.x * 4;
    int tx = tid & 15, ty = tid >> 4;

    #pragma unroll
    for (int s = 0; s < 8; s++) {
        int lin = tid + s * 256;
        int i = lin >> 7, q = lin & 127;
        int gc = (i >> 2) * 512 + d0 + (i & 3);
        float4 v = __ldg((const float4*)(w_hh + (size_t)gc * 512 + q * 4));
        w_s[q*4+0][i]=v.x; w_s[q*4+1][i]=v.y; w_s[q*4+2][i]=v.z; w_s[q*4+3][i]=v.w;
    }
    if (tid < NB) s_start[tid] = d_start[tid];
    if (tid < T)  s_nt[tid] = d_nt[tid];
    for (int e = tid; e < 512; e += 256) c_s[e] = 0.f;
    __syncthreads();

    for (int t = 0; t < T; t++) {
        int nt = s_nt[t];
        int nt8 = (nt + 7) & ~7;
        bool rowok = (ty * 8) < nt8;
        const float* hc = (t & 1) ? d_hB : d_hA;
        float*       hw = (t & 1) ? d_hA : d_hB;

        unsigned long long acc[4] = {0ull, 0ull, 0ull, 0ull};
        for (int kc = 0; kc < 32; kc++) {
            #pragma unroll
            for (int s = 0; s < 2; s++) {
                int lin = tid + s * 256;
                int row = lin >> 2, q2 = lin & 3;
                if (row < nt8) {
                    float4 v = __ldcg((const float4*)(hc + (size_t)row * 512 + kc * 16 + q2 * 4));
                    hs[q2*4+0][row]=v.x; hs[q2*4+1][row]=v.y; hs[q2*4+2][row]=v.z; hs[q2*4+3][row]=v.w;
                }
            }
            __syncthreads();
            if (rowok) {
                #pragma unroll
                for (int k = 0; k < 16; k++) {
                    ulonglong2 h01 = *(const ulonglong2*)&hs[k][ty * 8];
                    ulonglong2 h23 = *(const ulonglong2*)&hs[k][ty * 8 + 4];
                    unsigned long long wd = dup2(w_s[kc * 16 + k][tx]);
                    fma2(acc[0], h01.x, wd);
                    fma2(acc[1], h01.y, wd);
                    fma2(acc[2], h23.x, wd);
                    fma2(acc[3], h23.y, wd);
                }
            }
            __syncthreads();
        }
        #pragma unroll
        for (int p = 0; p < 4; p++) {
            float2 f = unpk(acc[p]);
            hs[tx][ty * 8 + p * 2 + 0] = f.x;
            hs[tx][ty * 8 + p * 2 + 1] = f.y;
        }
        __syncthreads();
        for (int e = tid; e < 512; e += 256) {
            int b = e >> 2, dd = e & 3;
            if (b < nt) {
                size_t cidx = (size_t)(s_start[b] + t);
                const float* xp = d_xproj + cidx * G + d0 + dd;
                float g0 = hs[dd][b]      + __ldg(xp);
                float g1 = hs[4 + dd][b]  + __ldg(xp + 512);
                float g2 = hs[8 + dd][b]  + __ldg(xp + 1024);
                float g3 = hs[12 + dd][b] + __ldg(xp + 1536);
                float gi = 1.f / (1.f + __expf(-g0));
                float gf = 1.f / (1.f + __expf(-g1));
                float gg = tanhf(g2);
                float go = 1.f / (1.f + __expf(-g3));
                float c  = c_s[e];
                float cn = gf * c + gi * gg;
                float hn = go * tanhf(cn);
                c_s[e] = cn;
                __stcg(hw + (size_t)b * 512 + d0 + dd, hn);
                d_Hbuf[cidx * 512 + d0 + dd] = hn;
            }
        }
        if (t < T - 1) {
            unsigned int target = (unsigned int)(t + 1) * (unsigned int)gridDim.x;
            __syncthreads();
            if (tid == 0) {
                __threadfence();
                atomicAdd(&d_ctr, 1u);
                while (*(volatile unsigned int*)&d_ctr < target) __nanosleep(32);
                __threadfence();
            }
            __syncthreads();
        }
    }
}

// ---------------------------------------------------------------------------
extern "C" void kernel_launch(void* const* d_in, const int* in_sizes, int n_in,
                              void* d_out, int out_size)
{
    const float* feats  = (const float*)d_in[0];
    const int*   caps   = (const int*)  d_in[1];
    const int*   clen   = (const int*)  d_in[2];
    const float* emb    = (const float*)d_in[3];
    const float* att1_w = (const float*)d_in[4];
    const float* att1_b = (const float*)d_in[5];
    const float* w_ih   = (const float*)d_in[6];
    const float* w_hh   = (const float*)d_in[7];
    const float* b_ih   = (const float*)d_in[8];
    const float* b_hh   = (const float*)d_in[9];
    const float* word_w = (const float*)d_in[10];
    const float* word_b = (const float*)d_in[11];
    float* out = (float*)d_out;

    float *xproj, *Hbuf, *bias2;
    int *tok, *vrow, *Sp;
    cudaGetSymbolAddress((void**)&xproj, d_xproj);
    cudaGetSymbolAddress((void**)&Hbuf,  d_Hbuf);
    cudaGetSymbolAddress((void**)&bias2, d_bias2);
    cudaGetSymbolAddress((void**)&tok,   d_tok);
    cudaGetSymbolAddress((void**)&vrow,  d_vrow);
    cudaGetSymbolAddress((void**)&Sp,    d_S);

    const long long PRED = (long long)NB * T * V;
    int write_tail = ((long long)out_size >= PRED + NB * L + 2 * NB) ? 1 : 0;

    prep_kernel<<<1, NB>>>(clen, caps, b_ih, b_hh, out, write_tail);
    mean_kernel<<<NB, 256>>>(feats);
    h0_kernel<<<dim3(NB, 4), 256>>>(att1_w, att1_b);

    // xproj (compacted rows): emb[tok] @ w_ih^T + (b_ih+b_hh)
    gemm128<true, false><<<dim3(R / 128, G / 128), 256>>>(
        emb, E, tok, w_ih, bias2, xproj, G, nullptr, Sp, G, E);

    zerofill<<<R, 256>>>(out);

    lstm_persist<<<NB, 256>>>(w_hh);

    // word projection: tf32 tensor cores, compacted rows, scatter to out
    word_mma<<<dim3((R + 63) / 64, (V + 63) / 64), 256>>>(
        Hbuf, word_w, word_b, out, vrow, Sp);
}

// round 9
// speedup vs baseline: 2.3959x; 1.1207x over previous
#include <cuda_runtime.h>
#include <math.h>

constexpr int NB=128, NP=196, FEAT=2048, E=512, D=512, V=10000, L=52, T=51;
constexpr int G=2048, R=NB*T;

__device__ float d_fm[NB*FEAT];
__device__ float d_hA[NB*D];
__device__ float d_hB[NB*D];
__device__ float d_xproj[(size_t)R*G];
__device__ float d_Hbuf[(size_t)R*D];
__device__ int d_sortind[NB], d_dlen[NB], d_start[NB], d_nt[T];
__device__ int d_S;
__device__ int d_tok[R], d_vrow[R];
__device__ float d_bias2[G];
__device__ unsigned int d_ctr;   // grid-barrier counter, reset by prep each launch

__device__ __forceinline__ void fma2(unsigned long long &d,
                                     unsigned long long a, unsigned long long b){
    asm("fma.rn.f32x2 %0, %1, %2, %0;" : "+l"(d) : "l"(a), "l"(b));
}
__device__ __forceinline__ unsigned long long dup2(float v){
    unsigned long long r; asm("mov.b64 %0, {%1, %1};" : "=l"(r) : "f"(v)); return r;
}
__device__ __forceinline__ float2 unpk(unsigned long long v){
    float2 f; asm("mov.b64 {%0, %1}, %2;" : "=f"(f.x), "=f"(f.y) : "l"(v)); return f;
}
__device__ __forceinline__ unsigned tf32_of(float f){
    unsigned u; asm("cvt.rna.tf32.f32 %0, %1;" : "=r"(u) : "f"(f)); return u;
}
__device__ __forceinline__ void mma_tf32(float* c, const unsigned* a, const unsigned* b){
    asm("mma.sync.aligned.m16n8k8.row.col.f32.tf32.tf32.f32 "
        "{%0,%1,%2,%3}, {%4,%5,%6,%7}, {%8,%9}, {%0,%1,%2,%3};"
        : "+f"(c[0]),"+f"(c[1]),"+f"(c[2]),"+f"(c[3])
        : "r"(a[0]),"r"(a[1]),"r"(a[2]),"r"(a[3]),"r"(b[0]),"r"(b[1]));
}

// ---------------------------------------------------------------------------
__global__ void prep_kernel(const int* __restrict__ clen,
                            const int* __restrict__ caps,
                            const float* __restrict__ b_ih,
                            const float* __restrict__ b_hh,
                            float* __restrict__ out, int write_tail)
{
    __shared__ int s_len[NB], s_dl[NB];
    int tid = threadIdx.x;
    if (tid == 0) d_ctr = 0u;
    s_len[tid] = clen[tid];
    __syncthreads();
    int li = s_len[tid], rank = 0;
    for (int j = 0; j < NB; j++) {
        int lj = s_len[j];
        rank += (lj > li) || (lj == li && j < tid);
    }
    d_sortind[rank] = tid;
    __syncthreads();
    int src = d_sortind[tid];
    int dl  = s_len[src] - 1;
    d_dlen[tid] = dl;
    s_dl[tid] = dl;
    for (int r = tid; r < R; r += NB) { d_vrow[r] = 0; d_tok[r] = 0; }
    __syncthreads();
    if (tid < T) {
        int c = 0;
        for (int b = 0; b < NB; b++) c += (s_dl[b] > tid);
        d_nt[tid] = c;
    }
    int st = 0;
    for (int j = 0; j < tid; j++) st += s_dl[j];
    d_start[tid] = st;
    if (tid == NB - 1) d_S = st + dl;
    for (int t = 0; t < dl; t++) {
        d_vrow[st + t] = tid * T + t;
        d_tok[st + t]  = caps[src * L + t];
    }
    if (write_tail) {
        float* out_caps = out + (size_t)NB * T * V;
        float* out_dlen = out_caps + (size_t)NB * L;
        float* out_sort = out_dlen + NB;
        out_dlen[tid] = (float)dl;
        out_sort[tid] = (float)src;
        for (int j = 0; j < L; j++)
            out_caps[tid * L + j] = (float)caps[src * L + j];
    }
    for (int j = tid; j < G; j += NB) d_bias2[j] = b_ih[j] + b_hh[j];
}

// ---------------------------------------------------------------------------
__global__ void mean_kernel(const float* __restrict__ feats)
{
    int b = blockIdx.x, src = d_sortind[b], tid = threadIdx.x;
    const float* base = feats + (size_t)src * NP * FEAT;
    float acc[FEAT / 256];
    #pragma unroll
    for (int j = 0; j < FEAT / 256; j++) acc[j] = 0.f;
    for (int p = 0; p < NP; p++) {
        const float* row = base + (size_t)p * FEAT;
        #pragma unroll
        for (int j = 0; j < FEAT / 256; j++) acc[j] += __ldg(&row[tid + j * 256]);
    }
    #pragma unroll
    for (int j = 0; j < FEAT / 256; j++)
        d_fm[b * FEAT + tid + j * 256] = acc[j] * (1.f / NP);
}

// ---------------------------------------------------------------------------
__global__ void h0_kernel(const float* __restrict__ att1_w,
                          const float* __restrict__ att1_b)
{
    __shared__ float s_fm[FEAT];
    int b = blockIdx.x, c0 = blockIdx.y * 128;
    for (int i = threadIdx.x; i < FEAT; i += 256) s_fm[i] = d_fm[b * FEAT + i];
    __syncthreads();
    int warp = threadIdx.x >> 5, lane = threadIdx.x & 31;
    for (int cc = warp; cc < 128; cc += 8) {
        int col = c0 + cc;
        const float4* wr = (const float4*)(att1_w + (size_t)col * FEAT);
        float s = 0.f;
        for (int k = lane; k < FEAT / 4; k += 32) {
            float4 w = __ldg(&wr[k]);
            float4 f = *(const float4*)&s_fm[k * 4];
            s += w.x * f.x + w.y * f.y + w.z * f.z + w.w * f.w;
        }
        #pragma unroll
        for (int o = 16; o; o >>= 1) s += __shfl_down_sync(~0u, s, o);
        if (!lane) d_hA[b * D + col] = s + __ldg(&att1_b[col]);
    }
}

// ---------------------------------------------------------------------------
// fp32 f32x2 GEMM (used for xproj). Proven in rounds 5/7.
// ---------------------------------------------------------------------------
template<bool GA, bool SCAT>
__global__ __launch_bounds__(256, 2) void gemm128(
    const float* __restrict__ A, int lda, const int* __restrict__ aIdx,
    const float* __restrict__ Bm, const float* __restrict__ bias,
    float* __restrict__ Cout, int ldc, const int* __restrict__ outIdx,
    const int* __restrict__ MvP, int N, int K)
{
    __shared__ __align__(16) float As[2][16][132];
    __shared__ __align__(16) float Bs[2][16][132];
    __shared__ int s_src[128];

    int m0 = blockIdx.x * 128, n0 = blockIdx.y * 128;
    int Mv = MvP ? __ldg(MvP) : 0x7fffffff;
    if (m0 >= Mv) return;

    int tid = threadIdx.x;
    if (tid < 128) s_src[tid] = GA ? __ldg(&aIdx[m0 + tid]) : (m0 + tid);
    __syncthreads();

    int tx = tid & 15, ty = tid >> 4;
    int tx4 = tx * 4, ty4 = ty * 4;
    int j1 = tid + 256;
    int r0 = tid >> 2, q0 = tid & 3;
    int r1 = j1 >> 2,  q1 = j1 & 3;
    const float* Ar0 = A + (size_t)s_src[r0] * lda + q0 * 4;
    const float* Ar1 = A + (size_t)s_src[r1] * lda + q1 * 4;
    bool bok0 = (n0 + r0) < N, bok1 = (n0 + r1) < N;
    const float* Br0 = Bm + (size_t)(n0 + r0) * K + q0 * 4;
    const float* Br1 = Bm + (size_t)(n0 + r1) * K + q1 * 4;
    const float4 z4 = make_float4(0.f, 0.f, 0.f, 0.f);

    unsigned long long acc[4][8];
    #pragma unroll
    for (int p = 0; p < 4; p++)
        #pragma unroll
        for (int j = 0; j < 8; j++) acc[p][j] = 0ull;

    float4 ra0 = __ldg((const float4*)Ar0);
    float4 ra1 = __ldg((const float4*)Ar1);
    float4 rb0 = bok0 ? __ldg((const float4*)Br0) : z4;
    float4 rb1 = bok1 ? __ldg((const float4*)Br1) : z4;
    As[0][q0*4+0][r0]=ra0.x; As[0][q0*4+1][r0]=ra0.y; As[0][q0*4+2][r0]=ra0.z; As[0][q0*4+3][r0]=ra0.w;
    As[0][q1*4+0][r1]=ra1.x; As[0][q1*4+1][r1]=ra1.y; As[0][q1*4+2][r1]=ra1.z; As[0][q1*4+3][r1]=ra1.w;
    Bs[0][q0*4+0][r0]=rb0.x; Bs[0][q0*4+1][r0]=rb0.y; Bs[0][q0*4+2][r0]=rb0.z; Bs[0][q0*4+3][r0]=rb0.w;
    Bs[0][q1*4+0][r1]=rb1.x; Bs[0][q1*4+1][r1]=rb1.y; Bs[0][q1*4+2][r1]=rb1.z; Bs[0][q1*4+3][r1]=rb1.w;
    __syncthreads();

    const int KT = K / 16;
    for (int kt = 0; kt < KT; kt++) {
        int cur = kt & 1;
        if (kt + 1 < KT) {
            int ko = (kt + 1) * 16;
            ra0 = __ldg((const float4*)(Ar0 + ko));
            ra1 = __ldg((const float4*)(Ar1 + ko));
            rb0 = bok0 ? __ldg((const float4*)(Br0 + ko)) : z4;
            rb1 = bok1 ? __ldg((const float4*)(Br1 + ko)) : z4;
        }
        #pragma unroll
        for (int k = 0; k < 16; k++) {
            ulonglong2 a01 = *(const ulonglong2*)&As[cur][k][ty4];
            ulonglong2 a23 = *(const ulonglong2*)&As[cur][k][ty4 + 64];
            float4 b0 = *(const float4*)&Bs[cur][k][tx4];
            float4 b1 = *(const float4*)&Bs[cur][k][tx4 + 64];
            unsigned long long pa[4] = {a01.x, a01.y, a23.x, a23.y};
            unsigned long long pb[8] = {dup2(b0.x), dup2(b0.y), dup2(b0.z), dup2(b0.w),
                                        dup2(b1.x), dup2(b1.y), dup2(b1.z), dup2(b1.w)};
            #pragma unroll
            for (int p = 0; p < 4; p++)
                #pragma unroll
                for (int j = 0; j < 8; j++)
                    fma2(acc[p][j], pa[p], pb[j]);
        }
        if (kt + 1 < KT) {
            int nb = 1 - cur;
            As[nb][q0*4+0][r0]=ra0.x; As[nb][q0*4+1][r0]=ra0.y; As[nb][q0*4+2][r0]=ra0.z; As[nb][q0*4+3][r0]=ra0.w;
            As[nb][q1*4+0][r1]=ra1.x; As[nb][q1*4+1][r1]=ra1.y; As[nb][q1*4+2][r1]=ra1.z; As[nb][q1*4+3][r1]=ra1.w;
            Bs[nb][q0*4+0][r0]=rb0.x; Bs[nb][q0*4+1][r0]=rb0.y; Bs[nb][q0*4+2][r0]=rb0.z; Bs[nb][q0*4+3][r0]=rb0.w;
            Bs[nb][q1*4+0][r1]=rb1.x; Bs[nb][q1*4+1][r1]=rb1.y; Bs[nb][q1*4+2][r1]=rb1.z; Bs[nb][q1*4+3][r1]=rb1.w;
        }
        __syncthreads();
    }

    bool cok0 = (n0 + tx4) < N, cok1 = (n0 + tx4 + 64) < N;
    float4 bi0 = z4, bi1 = z4;
    if (bias) {
        if (cok0) bi0 = __ldg((const float4*)(bias + n0 + tx4));
        if (cok1) bi1 = __ldg((const float4*)(bias + n0 + tx4 + 64));
    }
    #pragma unroll
    for (int p = 0; p < 4; p++) {
        int rbase = m0 + ((p < 2) ? (ty4 + 2 * p) : (64 + ty4 + 2 * (p - 2)));
        float2 u[8];
        #pragma unroll
        for (int j = 0; j < 8; j++) u[j] = unpk(acc[p][j]);
        float4 lo0 = make_float4(u[0].x+bi0.x, u[1].x+bi0.y, u[2].x+bi0.z, u[3].x+bi0.w);
        float4 lo1 = make_float4(u[4].x+bi1.x, u[5].x+bi1.y, u[6].x+bi1.z, u[7].x+bi1.w);
        float4 hi0 = make_float4(u[0].y+bi0.x, u[1].y+bi0.y, u[2].y+bi0.z, u[3].y+bi0.w);
        float4 hi1 = make_float4(u[4].y+bi1.x, u[5].y+bi1.y, u[6].y+bi1.z, u[7].y+bi1.w);
        if (!SCAT || rbase < Mv) {
            size_t orow = SCAT ? (size_t)__ldg(&outIdx[rbase]) : (size_t)rbase;
            if (cok0) *(float4*)(Cout + orow * ldc + n0 + tx4)      = lo0;
            if (cok1) *(float4*)(Cout + orow * ldc + n0 + tx4 + 64) = lo1;
        }
        int rh = rbase + 1;
        if (!SCAT || rh < Mv) {
            size_t orow = SCAT ? (size_t)__ldg(&outIdx[rh]) : (size_t)rh;
            if (cok0) *(float4*)(Cout + orow * ldc + n0 + tx4)      = hi0;
            if (cok1) *(float4*)(Cout + orow * ldc + n0 + tx4 + 64) = hi1;
        }
    }
}

// ---------------------------------------------------------------------------
// tf32 word projection v2: row-major smem with stride-36 padding.
// Gather bank = 4*(lane>>2) + (lane&3) + const -> all 32 banks, conflict-free.
// Stores are STS.128. 64x64x32 tiles, 8 warps (2m x 4n), double-buffered.
// Only changed kernel vs the round-7 passing source.
// ---------------------------------------------------------------------------
__global__ __launch_bounds__(256) void word_mma(
    const float* __restrict__ A,       // Hbuf [R][512]
    const float* __restrict__ Bm,      // word_w [V][512]
    const float* __restrict__ bias,    // word_b [V]
    float* __restrict__ Cout,          // out [R][V]
    const int* __restrict__ outIdx,    // vrow
    const int* __restrict__ MvP)       // d_S
{
    constexpr int ST = 36;                       // row stride (words), 4 mod 32
    __shared__ __align__(16) unsigned As[2][64 * ST];
    __shared__ __align__(16) unsigned Bs[2][64 * ST];

    int m0 = blockIdx.x * 64, n0 = blockIdx.y * 64;
    int Mv = __ldg(MvP);
    if (m0 >= Mv) return;

    int tid = threadIdx.x, lane = tid & 31, w = tid >> 5;
    int wm = w & 1, wn = w >> 1;          // 2 x 4 warp grid
    int lrow = tid >> 3, q = tid & 7;     // each thread: rows lrow & lrow+32, one float4
    const float4 z4 = make_float4(0.f, 0.f, 0.f, 0.f);

    const float4* Ag0 = (const float4*)(A + (size_t)(m0 + lrow)      * D) + q;
    const float4* Ag1 = (const float4*)(A + (size_t)(m0 + lrow + 32) * D) + q;
    int br0 = n0 + lrow, br1 = n0 + lrow + 32;
    bool bok0 = br0 < V, bok1 = br1 < V;
    const float4* Bg0 = (const float4*)(Bm + (size_t)(bok0 ? br0 : 0) * D) + q;
    const float4* Bg1 = (const float4*)(Bm + (size_t)(bok1 ? br1 : 0) * D) + q;

    int s0 = lrow * ST + q * 4;                  // 16B aligned (36 ≡ 0 mod 4)
    int s1 = (lrow + 32) * ST + q * 4;

    float acc[2][2][4];
    #pragma unroll
    for (int i = 0; i < 2; i++)
        #pragma unroll
        for (int j = 0; j < 2; j++)
            #pragma unroll
            for (int r = 0; r < 4; r++) acc[i][j][r] = 0.f;

    float4 pa0 = __ldg(Ag0), pa1 = __ldg(Ag1);
    float4 pb0 = bok0 ? __ldg(Bg0) : z4;
    float4 pb1 = bok1 ? __ldg(Bg1) : z4;
    {
        uint4 u;
        u.x=tf32_of(pa0.x); u.y=tf32_of(pa0.y); u.z=tf32_of(pa0.z); u.w=tf32_of(pa0.w);
        *(uint4*)&As[0][s0] = u;
        u.x=tf32_of(pa1.x); u.y=tf32_of(pa1.y); u.z=tf32_of(pa1.z); u.w=tf32_of(pa1.w);
        *(uint4*)&As[0][s1] = u;
        u.x=tf32_of(pb0.x); u.y=tf32_of(pb0.y); u.z=tf32_of(pb0.z); u.w=tf32_of(pb0.w);
        *(uint4*)&Bs[0][s0] = u;
        u.x=tf32_of(pb1.x); u.y=tf32_of(pb1.y); u.z=tf32_of(pb1.z); u.w=tf32_of(pb1.w);
        *(uint4*)&Bs[0][s1] = u;
    }
    __syncthreads();

    int g = lane >> 2, t4 = lane & 3;
    const int KT = D / 32;   // 16 chunks of k=32
    for (int kt = 0; kt < KT; kt++) {
        int cur = kt & 1;
        if (kt + 1 < KT) {
            int ko = (kt + 1) * 8;               // float4 units
            pa0 = __ldg(Ag0 + ko); pa1 = __ldg(Ag1 + ko);
            pb0 = bok0 ? __ldg(Bg0 + ko) : z4;
            pb1 = bok1 ? __ldg(Bg1 + ko) : z4;
        }
        #pragma unroll
        for (int ks = 0; ks < 4; ks++) {
            int kb = ks * 8;
            unsigned af[2][4], bf[2][2];
            #pragma unroll
            for (int i = 0; i < 2; i++) {
                int base = (wm * 32 + i * 16 + g) * ST + kb + t4;
                af[i][0] = As[cur][base];
                af[i][1] = As[cur][base + 8 * ST];
                af[i][2] = As[cur][base + 4];
                af[i][3] = As[cur][base + 8 * ST + 4];
            }
            #pragma unroll
            for (int j = 0; j < 2; j++) {
                int base = ((wn * 2 + j) * 8 + g) * ST + kb + t4;
                bf[j][0] = Bs[cur][base];
                bf[j][1] = Bs[cur][base + 4];
            }
            #pragma unroll
            for (int i = 0; i < 2; i++)
                #pragma unroll
                for (int j = 0; j < 2; j++)
                    mma_tf32(acc[i][j], af[i], bf[j]);
        }
        if (kt + 1 < KT) {
            int nb = 1 - cur;
            uint4 u;
            u.x=tf32_of(pa0.x); u.y=tf32_of(pa0.y); u.z=tf32_of(pa0.z); u.w=tf32_of(pa0.w);
            *(uint4*)&As[nb][s0] = u;
            u.x=tf32_of(pa1.x); u.y=tf32_of(pa1.y); u.z=tf32_of(pa1.z); u.w=tf32_of(pa1.w);
            *(uint4*)&As[nb][s1] = u;
            u.x=tf32_of(pb0.x); u.y=tf32_of(pb0.y); u.z=tf32_of(pb0.z); u.w=tf32_of(pb0.w);
            *(uint4*)&Bs[nb][s0] = u;
            u.x=tf32_of(pb1.x); u.y=tf32_of(pb1.y); u.z=tf32_of(pb1.z); u.w=tf32_of(pb1.w);
            *(uint4*)&Bs[nb][s1] = u;
        }
        __syncthreads();
    }

    int r0 = lane >> 2, tg = lane & 3;
    #pragma unroll
    for (int i = 0; i < 2; i++) {
        int mloc = (wm * 2 + i) * 16 + r0;
        #pragma unroll
        for (int h = 0; h < 2; h++) {
            int gr = m0 + mloc + h * 8;
            if (gr < Mv) {
                size_t orow = (size_t)__ldg(&outIdx[gr]);
                float* outr = Cout + orow * V;
                #pragma unroll
                for (int j = 0; j < 2; j++) {
                    int gc = n0 + (wn * 2 + j) * 8 + tg * 2;
                    if (gc < V) {
                        float b0 = __ldg(&bias[gc]), b1 = __ldg(&bias[gc + 1]);
                        float2 v;
                        v.x = acc[i][j][h * 2 + 0] + b0;
                        v.y = acc[i][j][h * 2 + 1] + b1;
                        *(float2*)(outr + gc) = v;
                    }
                }
            }
        }
    }
}

// ---------------------------------------------------------------------------
__global__ void zerofill(float* __restrict__ out)
{
    int r = blockIdx.x, b = r / T, t = r - b * T;
    if (t < d_dlen[b]) return;
    float4* p = (float4*)(out + (size_t)r * V);
    float4 z = make_float4(0.f, 0.f, 0.f, 0.f);
    for (int i = threadIdx.x; i < V / 4; i += blockDim.x) p[i] = z;
}

// ---------------------------------------------------------------------------
// persistent LSTM — byte-identical to the round-7 PASSING version.
// ---------------------------------------------------------------------------
__global__ __launch_bounds__(256) void lstm_persist(const float* __restrict__ w_hh)
{
    __shared__ float w_s[512][16];
    __shared__ __align__(16) float hs[16][132];
    __shared__ float c_s[512];
    __shared__ int s_start[NB];
    __shared__ int s_nt[T];

    int tid = threadIdx.x, d0 = blockIdx.x * 4;
    int tx = tid & 15, ty = tid >> 4;

    #pragma unroll
    for (int s = 0; s < 8; s++) {
        int lin = tid + s * 256;
        int i = lin >> 7, q = lin & 127;
        int gc = (i >> 2) * 512 + d0 + (i & 3);
        float4 v = __ldg((const float4*)(w_hh + (size_t)gc * 512 + q * 4));
        w_s[q*4+0][i]=v.x; w_s[q*4+1][i]=v.y; w_s[q*4+2][i]=v.z; w_s[q*4+3][i]=v.w;
    }
    if (tid < NB) s_start[tid] = d_start[tid];
    if (tid < T)  s_nt[tid] = d_nt[tid];
    for (int e = tid; e < 512; e += 256) c_s[e] = 0.f;
    __syncthreads();

    for (int t = 0; t < T; t++) {
        int nt = s_nt[t];
        int nt8 = (nt + 7) & ~7;
        bool rowok = (ty * 8) < nt8;
        const float* hc = (t & 1) ? d_hB : d_hA;
        float*       hw = (t & 1) ? d_hA : d_hB;

        unsigned long long acc[4] = {0ull, 0ull, 0ull, 0ull};
        for (int kc = 0; kc < 32; kc++) {
            #pragma unroll
            for (int s = 0; s < 2; s++) {
                int lin = tid + s * 256;
                int row = lin >> 2, q2 = lin & 3;
                if (row < nt8) {
                    float4 v = __ldcg((const float4*)(hc + (size_t)row * 512 + kc * 16 + q2 * 4));
                    hs[q2*4+0][row]=v.x; hs[q2*4+1][row]=v.y; hs[q2*4+2][row]=v.z; hs[q2*4+3][row]=v.w;
                }
            }
            __syncthreads();
            if (rowok) {
                #pragma unroll
                for (int k = 0; k < 16; k++) {
                    ulonglong2 h01 = *(const ulonglong2*)&hs[k][ty * 8];
                    ulonglong2 h23 = *(const ulonglong2*)&hs[k][ty * 8 + 4];
                    unsigned long long wd = dup2(w_s[kc * 16 + k][tx]);
                    fma2(acc[0], h01.x, wd);
                    fma2(acc[1], h01.y, wd);
                    fma2(acc[2], h23.x, wd);
                    fma2(acc[3], h23.y, wd);
                }
            }
            __syncthreads();
        }
        #pragma unroll
        for (int p = 0; p < 4; p++) {
            float2 f = unpk(acc[p]);
            hs[tx][ty * 8 + p * 2 + 0] = f.x;
            hs[tx][ty * 8 + p * 2 + 1] = f.y;
        }
        __syncthreads();
        for (int e = tid; e < 512; e += 256) {
            int b = e >> 2, dd = e & 3;
            if (b < nt) {
                size_t cidx = (size_t)(s_start[b] + t);
                const float* xp = d_xproj + cidx * G + d0 + dd;
                float g0 = hs[dd][b]      + __ldg(xp);
                float g1 = hs[4 + dd][b]  + __ldg(xp + 512);
                float g2 = hs[8 + dd][b]  + __ldg(xp + 1024);
                float g3 = hs[12 + dd][b] + __ldg(xp + 1536);
                float gi = 1.f / (1.f + __expf(-g0));
                float gf = 1.f / (1.f + __expf(-g1));
                float gg = tanhf(g2);
                float go = 1.f / (1.f + __expf(-g3));
                float c  = c_s[e];
                float cn = gf * c + gi * gg;
                float hn = go * tanhf(cn);
                c_s[e] = cn;
                __stcg(hw + (size_t)b * 512 + d0 + dd, hn);
                d_Hbuf[cidx * 512 + d0 + dd] = hn;
            }
        }
        if (t < T - 1) {
            unsigned int target = (unsigned int)(t + 1) * (unsigned int)gridDim.x;
            __syncthreads();
            if (tid == 0) {
                __threadfence();
                atomicAdd(&d_ctr, 1u);
                while (*(volatile unsigned int*)&d_ctr < target) __nanosleep(32);
                __threadfence();
            }
            __syncthreads();
        }
    }
}

// ---------------------------------------------------------------------------
extern "C" void kernel_launch(void* const* d_in, const int* in_sizes, int n_in,
                              void* d_out, int out_size)
{
    const float* feats  = (const float*)d_in[0];
    const int*   caps   = (const int*)  d_in[1];
    const int*   clen   = (const int*)  d_in[2];
    const float* emb    = (const float*)d_in[3];
    const float* att1_w = (const float*)d_in[4];
    const float* att1_b = (const float*)d_in[5];
    const float* w_ih   = (const float*)d_in[6];
    const float* w_hh   = (const float*)d_in[7];
    const float* b_ih   = (const float*)d_in[8];
    const float* b_hh   = (const float*)d_in[9];
    const float* word_w = (const float*)d_in[10];
    const float* word_b = (const float*)d_in[11];
    float* out = (float*)d_out;

    float *xproj, *Hbuf, *bias2;
    int *tok, *vrow, *Sp;
    cudaGetSymbolAddress((void**)&xproj, d_xproj);
    cudaGetSymbolAddress((void**)&Hbuf,  d_Hbuf);
    cudaGetSymbolAddress((void**)&bias2, d_bias2);
    cudaGetSymbolAddress((void**)&tok,   d_tok);
    cudaGetSymbolAddress((void**)&vrow,  d_vrow);
    cudaGetSymbolAddress((void**)&Sp,    d_S);

    const long long PRED = (long long)NB * T * V;
    int write_tail = ((long long)out_size >= PRED + NB * L + 2 * NB) ? 1 : 0;

    prep_kernel<<<1, NB>>>(clen, caps, b_ih, b_hh, out, write_tail);
    mean_kernel<<<NB, 256>>>(feats);
    h0_kernel<<<dim3(NB, 4), 256>>>(att1_w, att1_b);

    // xproj (compacted rows): emb[tok] @ w_ih^T + (b_ih+b_hh)
    gemm128<true, false><<<dim3(R / 128, G / 128), 256>>>(
        emb, E, tok, w_ih, bias2, xproj, G, nullptr, Sp, G, E);

    zerofill<<<R, 256>>>(out);

    lstm_persist<<<NB, 256>>>(w_hh);

    // word projection: tf32 tensor cores, compacted rows, scatter to out
    word_mma<<<dim3((R + 63) / 64, (V + 63) / 64), 256>>>(
        Hbuf, word_w, word_b, out, vrow, Sp);
}

// round 10
// speedup vs baseline: 3.1860x; 1.3298x over previous
#include <cuda_runtime.h>
#include <math.h>

constexpr int NB=128, NP=196, FEAT=2048, E=512, D=512, V=10000, L=52, T=51;
constexpr int G=2048, R=NB*T;

__device__ float d_fm[NB*FEAT];
__device__ float d_hA[NB*D];
__device__ float d_hB[NB*D];
__device__ float d_xproj[(size_t)R*G];
__device__ float d_Hbuf[(size_t)R*D];
__device__ int d_sortind[NB], d_dlen[NB], d_start[NB], d_nt[T];
__device__ int d_S;
__device__ int d_tok[R], d_vrow[R];
__device__ float d_bias2[G];
__device__ unsigned int d_ctr;   // grid-barrier counter, reset by prep each launch

__device__ __forceinline__ void fma2(unsigned long long &d,
                                     unsigned long long a, unsigned long long b){
    asm("fma.rn.f32x2 %0, %1, %2, %0;" : "+l"(d) : "l"(a), "l"(b));
}
__device__ __forceinline__ unsigned long long dup2(float v){
    unsigned long long r; asm("mov.b64 %0, {%1, %1};" : "=l"(r) : "f"(v)); return r;
}
__device__ __forceinline__ float2 unpk(unsigned long long v){
    float2 f; asm("mov.b64 {%0, %1}, %2;" : "=f"(f.x), "=f"(f.y) : "l"(v)); return f;
}
__device__ __forceinline__ unsigned tf32_of(float f){
    unsigned u; asm("cvt.rna.tf32.f32 %0, %1;" : "=r"(u) : "f"(f)); return u;
}
__device__ __forceinline__ void mma_tf32(float* c, const unsigned* a, const unsigned* b){
    asm("mma.sync.aligned.m16n8k8.row.col.f32.tf32.tf32.f32 "
        "{%0,%1,%2,%3}, {%4,%5,%6,%7}, {%8,%9}, {%0,%1,%2,%3};"
        : "+f"(c[0]),"+f"(c[1]),"+f"(c[2]),"+f"(c[3])
        : "r"(a[0]),"r"(a[1]),"r"(a[2]),"r"(a[3]),"r"(b[0]),"r"(b[1]));
}

// ---------------------------------------------------------------------------
__global__ void prep_kernel(const int* __restrict__ clen,
                            const int* __restrict__ caps,
                            const float* __restrict__ b_ih,
                            const float* __restrict__ b_hh,
                            float* __restrict__ out, int write_tail)
{
    __shared__ int s_len[NB], s_dl[NB];
    int tid = threadIdx.x;
    if (tid == 0) d_ctr = 0u;
    s_len[tid] = clen[tid];
    __syncthreads();
    int li = s_len[tid], rank = 0;
    for (int j = 0; j < NB; j++) {
        int lj = s_len[j];
        rank += (lj > li) || (lj == li && j < tid);
    }
    d_sortind[rank] = tid;
    __syncthreads();
    int src = d_sortind[tid];
    int dl  = s_len[src] - 1;
    d_dlen[tid] = dl;
    s_dl[tid] = dl;
    for (int r = tid; r < R; r += NB) { d_vrow[r] = 0; d_tok[r] = 0; }
    __syncthreads();
    if (tid < T) {
        int c = 0;
        for (int b = 0; b < NB; b++) c += (s_dl[b] > tid);
        d_nt[tid] = c;
    }
    int st = 0;
    for (int j = 0; j < tid; j++) st += s_dl[j];
    d_start[tid] = st;
    if (tid == NB - 1) d_S = st + dl;
    for (int t = 0; t < dl; t++) {
        d_vrow[st + t] = tid * T + t;
        d_tok[st + t]  = caps[src * L + t];
    }
    if (write_tail) {
        float* out_caps = out + (size_t)NB * T * V;
        float* out_dlen = out_caps + (size_t)NB * L;
        float* out_sort = out_dlen + NB;
        out_dlen[tid] = (float)dl;
        out_sort[tid] = (float)src;
        for (int j = 0; j < L; j++)
            out_caps[tid * L + j] = (float)caps[src * L + j];
    }
    for (int j = tid; j < G; j += NB) d_bias2[j] = b_ih[j] + b_hh[j];
}

// ---------------------------------------------------------------------------
__global__ void mean_kernel(const float* __restrict__ feats)
{
    int b = blockIdx.x, src = d_sortind[b], tid = threadIdx.x;
    const float* base = feats + (size_t)src * NP * FEAT;
    float acc[FEAT / 256];
    #pragma unroll
    for (int j = 0; j < FEAT / 256; j++) acc[j] = 0.f;
    for (int p = 0; p < NP; p++) {
        const float* row = base + (size_t)p * FEAT;
        #pragma unroll
        for (int j = 0; j < FEAT / 256; j++) acc[j] += __ldg(&row[tid + j * 256]);
    }
    #pragma unroll
    for (int j = 0; j < FEAT / 256; j++)
        d_fm[b * FEAT + tid + j * 256] = acc[j] * (1.f / NP);
}

// ---------------------------------------------------------------------------
__global__ void h0_kernel(const float* __restrict__ att1_w,
                          const float* __restrict__ att1_b)
{
    __shared__ float s_fm[FEAT];
    int b = blockIdx.x, c0 = blockIdx.y * 128;
    for (int i = threadIdx.x; i < FEAT; i += 256) s_fm[i] = d_fm[b * FEAT + i];
    __syncthreads();
    int warp = threadIdx.x >> 5, lane = threadIdx.x & 31;
    for (int cc = warp; cc < 128; cc += 8) {
        int col = c0 + cc;
        const float4* wr = (const float4*)(att1_w + (size_t)col * FEAT);
        float s = 0.f;
        for (int k = lane; k < FEAT / 4; k += 32) {
            float4 w = __ldg(&wr[k]);
            float4 f = *(const float4*)&s_fm[k * 4];
            s += w.x * f.x + w.y * f.y + w.z * f.z + w.w * f.w;
        }
        #pragma unroll
        for (int o = 16; o; o >>= 1) s += __shfl_down_sync(~0u, s, o);
        if (!lane) d_hA[b * D + col] = s + __ldg(&att1_b[col]);
    }
}

// ---------------------------------------------------------------------------
// fp32 f32x2 GEMM (used for xproj). Proven in rounds 5/7/9.
// ---------------------------------------------------------------------------
template<bool GA, bool SCAT>
__global__ __launch_bounds__(256, 2) void gemm128(
    const float* __restrict__ A, int lda, const int* __restrict__ aIdx,
    const float* __restrict__ Bm, const float* __restrict__ bias,
    float* __restrict__ Cout, int ldc, const int* __restrict__ outIdx,
    const int* __restrict__ MvP, int N, int K)
{
    __shared__ __align__(16) float As[2][16][132];
    __shared__ __align__(16) float Bs[2][16][132];
    __shared__ int s_src[128];

    int m0 = blockIdx.x * 128, n0 = blockIdx.y * 128;
    int Mv = MvP ? __ldg(MvP) : 0x7fffffff;
    if (m0 >= Mv) return;

    int tid = threadIdx.x;
    if (tid < 128) s_src[tid] = GA ? __ldg(&aIdx[m0 + tid]) : (m0 + tid);
    __syncthreads();

    int tx = tid & 15, ty = tid >> 4;
    int tx4 = tx * 4, ty4 = ty * 4;
    int j1 = tid + 256;
    int r0 = tid >> 2, q0 = tid & 3;
    int r1 = j1 >> 2,  q1 = j1 & 3;
    const float* Ar0 = A + (size_t)s_src[r0] * lda + q0 * 4;
    const float* Ar1 = A + (size_t)s_src[r1] * lda + q1 * 4;
    bool bok0 = (n0 + r0) < N, bok1 = (n0 + r1) < N;
    const float* Br0 = Bm + (size_t)(n0 + r0) * K + q0 * 4;
    const float* Br1 = Bm + (size_t)(n0 + r1) * K + q1 * 4;
    const float4 z4 = make_float4(0.f, 0.f, 0.f, 0.f);

    unsigned long long acc[4][8];
    #pragma unroll
    for (int p = 0; p < 4; p++)
        #pragma unroll
        for (int j = 0; j < 8; j++) acc[p][j] = 0ull;

    float4 ra0 = __ldg((const float4*)Ar0);
    float4 ra1 = __ldg((const float4*)Ar1);
    float4 rb0 = bok0 ? __ldg((const float4*)Br0) : z4;
    float4 rb1 = bok1 ? __ldg((const float4*)Br1) : z4;
    As[0][q0*4+0][r0]=ra0.x; As[0][q0*4+1][r0]=ra0.y; As[0][q0*4+2][r0]=ra0.z; As[0][q0*4+3][r0]=ra0.w;
    As[0][q1*4+0][r1]=ra1.x; As[0][q1*4+1][r1]=ra1.y; As[0][q1*4+2][r1]=ra1.z; As[0][q1*4+3][r1]=ra1.w;
    Bs[0][q0*4+0][r0]=rb0.x; Bs[0][q0*4+1][r0]=rb0.y; Bs[0][q0*4+2][r0]=rb0.z; Bs[0][q0*4+3][r0]=rb0.w;
    Bs[0][q1*4+0][r1]=rb1.x; Bs[0][q1*4+1][r1]=rb1.y; Bs[0][q1*4+2][r1]=rb1.z; Bs[0][q1*4+3][r1]=rb1.w;
    __syncthreads();

    const int KT = K / 16;
    for (int kt = 0; kt < KT; kt++) {
        int cur = kt & 1;
        if (kt + 1 < KT) {
            int ko = (kt + 1) * 16;
            ra0 = __ldg((const float4*)(Ar0 + ko));
            ra1 = __ldg((const float4*)(Ar1 + ko));
            rb0 = bok0 ? __ldg((const float4*)(Br0 + ko)) : z4;
            rb1 = bok1 ? __ldg((const float4*)(Br1 + ko)) : z4;
        }
        #pragma unroll
        for (int k = 0; k < 16; k++) {
            ulonglong2 a01 = *(const ulonglong2*)&As[cur][k][ty4];
            ulonglong2 a23 = *(const ulonglong2*)&As[cur][k][ty4 + 64];
            float4 b0 = *(const float4*)&Bs[cur][k][tx4];
            float4 b1 = *(const float4*)&Bs[cur][k][tx4 + 64];
            unsigned long long pa[4] = {a01.x, a01.y, a23.x, a23.y};
            unsigned long long pb[8] = {dup2(b0.x), dup2(b0.y), dup2(b0.z), dup2(b0.w),
                                        dup2(b1.x), dup2(b1.y), dup2(b1.z), dup2(b1.w)};
            #pragma unroll
            for (int p = 0; p < 4; p++)
                #pragma unroll
                for (int j = 0; j < 8; j++)
                    fma2(acc[p][j], pa[p], pb[j]);
        }
        if (kt + 1 < KT) {
            int nb = 1 - cur;
            As[nb][q0*4+0][r0]=ra0.x; As[nb][q0*4+1][r0]=ra0.y; As[nb][q0*4+2][r0]=ra0.z; As[nb][q0*4+3][r0]=ra0.w;
            As[nb][q1*4+0][r1]=ra1.x; As[nb][q1*4+1][r1]=ra1.y; As[nb][q1*4+2][r1]=ra1.z; As[nb][q1*4+3][r1]=ra1.w;
            Bs[nb][q0*4+0][r0]=rb0.x; Bs[nb][q0*4+1][r0]=rb0.y; Bs[nb][q0*4+2][r0]=rb0.z; Bs[nb][q0*4+3][r0]=rb0.w;
            Bs[nb][q1*4+0][r1]=rb1.x; Bs[nb][q1*4+1][r1]=rb1.y; Bs[nb][q1*4+2][r1]=rb1.z; Bs[nb][q1*4+3][r1]=rb1.w;
        }
        __syncthreads();
    }

    bool cok0 = (n0 + tx4) < N, cok1 = (n0 + tx4 + 64) < N;
    float4 bi0 = z4, bi1 = z4;
    if (bias) {
        if (cok0) bi0 = __ldg((const float4*)(bias + n0 + tx4));
        if (cok1) bi1 = __ldg((const float4*)(bias + n0 + tx4 + 64));
    }
    #pragma unroll
    for (int p = 0; p < 4; p++) {
        int rbase = m0 + ((p < 2) ? (ty4 + 2 * p) : (64 + ty4 + 2 * (p - 2)));
        float2 u[8];
        #pragma unroll
        for (int j = 0; j < 8; j++) u[j] = unpk(acc[p][j]);
        float4 lo0 = make_float4(u[0].x+bi0.x, u[1].x+bi0.y, u[2].x+bi0.z, u[3].x+bi0.w);
        float4 lo1 = make_float4(u[4].x+bi1.x, u[5].x+bi1.y, u[6].x+bi1.z, u[7].x+bi1.w);
        float4 hi0 = make_float4(u[0].y+bi0.x, u[1].y+bi0.y, u[2].y+bi0.z, u[3].y+bi0.w);
        float4 hi1 = make_float4(u[4].y+bi1.x, u[5].y+bi1.y, u[6].y+bi1.z, u[7].y+bi1.w);
        if (!SCAT || rbase < Mv) {
            size_t orow = SCAT ? (size_t)__ldg(&outIdx[rbase]) : (size_t)rbase;
            if (cok0) *(float4*)(Cout + orow * ldc + n0 + tx4)      = lo0;
            if (cok1) *(float4*)(Cout + orow * ldc + n0 + tx4 + 64) = lo1;
        }
        int rh = rbase + 1;
        if (!SCAT || rh < Mv) {
            size_t orow = SCAT ? (size_t)__ldg(&outIdx[rh]) : (size_t)rh;
            if (cok0) *(float4*)(Cout + orow * ldc + n0 + tx4)      = hi0;
            if (cok1) *(float4*)(Cout + orow * ldc + n0 + tx4 + 64) = hi1;
        }
    }
}

// ---------------------------------------------------------------------------
// tf32 word projection v2 — byte-identical to the round-9 PASSING version.
// ---------------------------------------------------------------------------
__global__ __launch_bounds__(256) void word_mma(
    const float* __restrict__ A,       // Hbuf [R][512]
    const float* __restrict__ Bm,      // word_w [V][512]
    const float* __restrict__ bias,    // word_b [V]
    float* __restrict__ Cout,          // out [R][V]
    const int* __restrict__ outIdx,    // vrow
    const int* __restrict__ MvP)       // d_S
{
    constexpr int ST = 36;                       // row stride (words), 4 mod 32
    __shared__ __align__(16) unsigned As[2][64 * ST];
    __shared__ __align__(16) unsigned Bs[2][64 * ST];

    int m0 = blockIdx.x * 64, n0 = blockIdx.y * 64;
    int Mv = __ldg(MvP);
    if (m0 >= Mv) return;

    int tid = threadIdx.x, lane = tid & 31, w = tid >> 5;
    int wm = w & 1, wn = w >> 1;          // 2 x 4 warp grid
    int lrow = tid >> 3, q = tid & 7;     // each thread: rows lrow & lrow+32, one float4
    const float4 z4 = make_float4(0.f, 0.f, 0.f, 0.f);

    const float4* Ag0 = (const float4*)(A + (size_t)(m0 + lrow)      * D) + q;
    const float4* Ag1 = (const float4*)(A + (size_t)(m0 + lrow + 32) * D) + q;
    int br0 = n0 + lrow, br1 = n0 + lrow + 32;
    bool bok0 = br0 < V, bok1 = br1 < V;
    const float4* Bg0 = (const float4*)(Bm + (size_t)(bok0 ? br0 : 0) * D) + q;
    const float4* Bg1 = (const float4*)(Bm + (size_t)(bok1 ? br1 : 0) * D) + q;

    int s0 = lrow * ST + q * 4;                  // 16B aligned (36 ≡ 0 mod 4)
    int s1 = (lrow + 32) * ST + q * 4;

    float acc[2][2][4];
    #pragma unroll
    for (int i = 0; i < 2; i++)
        #pragma unroll
        for (int j = 0; j < 2; j++)
            #pragma unroll
            for (int r = 0; r < 4; r++) acc[i][j][r] = 0.f;

    float4 pa0 = __ldg(Ag0), pa1 = __ldg(Ag1);
    float4 pb0 = bok0 ? __ldg(Bg0) : z4;
    float4 pb1 = bok1 ? __ldg(Bg1) : z4;
    {
        uint4 u;
        u.x=tf32_of(pa0.x); u.y=tf32_of(pa0.y); u.z=tf32_of(pa0.z); u.w=tf32_of(pa0.w);
        *(uint4*)&As[0][s0] = u;
        u.x=tf32_of(pa1.x); u.y=tf32_of(pa1.y); u.z=tf32_of(pa1.z); u.w=tf32_of(pa1.w);
        *(uint4*)&As[0][s1] = u;
        u.x=tf32_of(pb0.x); u.y=tf32_of(pb0.y); u.z=tf32_of(pb0.z); u.w=tf32_of(pb0.w);
        *(uint4*)&Bs[0][s0] = u;
        u.x=tf32_of(pb1.x); u.y=tf32_of(pb1.y); u.z=tf32_of(pb1.z); u.w=tf32_of(pb1.w);
        *(uint4*)&Bs[0][s1] = u;
    }
    __syncthreads();

    int g = lane >> 2, t4 = lane & 3;
    const int KT = D / 32;   // 16 chunks of k=32
    for (int kt = 0; kt < KT; kt++) {
        int cur = kt & 1;
        if (kt + 1 < KT) {
            int ko = (kt + 1) * 8;               // float4 units
            pa0 = __ldg(Ag0 + ko); pa1 = __ldg(Ag1 + ko);
            pb0 = bok0 ? __ldg(Bg0 + ko) : z4;
            pb1 = bok1 ? __ldg(Bg1 + ko) : z4;
        }
        #pragma unroll
        for (int ks = 0; ks < 4; ks++) {
            int kb = ks * 8;
            unsigned af[2][4], bf[2][2];
            #pragma unroll
            for (int i = 0; i < 2; i++) {
                int base = (wm * 32 + i * 16 + g) * ST + kb + t4;
                af[i][0] = As[cur][base];
                af[i][1] = As[cur][base + 8 * ST];
                af[i][2] = As[cur][base + 4];
                af[i][3] = As[cur][base + 8 * ST + 4];
            }
            #pragma unroll
            for (int j = 0; j < 2; j++) {
                int base = ((wn * 2 + j) * 8 + g) * ST + kb + t4;
                bf[j][0] = Bs[cur][base];
                bf[j][1] = Bs[cur][base + 4];
            }
            #pragma unroll
            for (int i = 0; i < 2; i++)
                #pragma unroll
                for (int j = 0; j < 2; j++)
                    mma_tf32(acc[i][j], af[i], bf[j]);
        }
        if (kt + 1 < KT) {
            int nb = 1 - cur;
            uint4 u;
            u.x=tf32_of(pa0.x); u.y=tf32_of(pa0.y); u.z=tf32_of(pa0.z); u.w=tf32_of(pa0.w);
            *(uint4*)&As[nb][s0] = u;
            u.x=tf32_of(pa1.x); u.y=tf32_of(pa1.y); u.z=tf32_of(pa1.z); u.w=tf32_of(pa1.w);
            *(uint4*)&As[nb][s1] = u;
            u.x=tf32_of(pb0.x); u.y=tf32_of(pb0.y); u.z=tf32_of(pb0.z); u.w=tf32_of(pb0.w);
            *(uint4*)&Bs[nb][s0] = u;
            u.x=tf32_of(pb1.x); u.y=tf32_of(pb1.y); u.z=tf32_of(pb1.z); u.w=tf32_of(pb1.w);
            *(uint4*)&Bs[nb][s1] = u;
        }
        __syncthreads();
    }

    int r0 = lane >> 2, tg = lane & 3;
    #pragma unroll
    for (int i = 0; i < 2; i++) {
        int mloc = (wm * 2 + i) * 16 + r0;
        #pragma unroll
        for (int h = 0; h < 2; h++) {
            int gr = m0 + mloc + h * 8;
            if (gr < Mv) {
                size_t orow = (size_t)__ldg(&outIdx[gr]);
                float* outr = Cout + orow * V;
                #pragma unroll
                for (int j = 0; j < 2; j++) {
                    int gc = n0 + (wn * 2 + j) * 8 + tg * 2;
                    if (gc < V) {
                        float b0 = __ldg(&bias[gc]), b1 = __ldg(&bias[gc + 1]);
                        float2 v;
                        v.x = acc[i][j][h * 2 + 0] + b0;
                        v.y = acc[i][j][h * 2 + 1] + b1;
                        *(float2*)(outr + gc) = v;
                    }
                }
            }
        }
    }
}

// ---------------------------------------------------------------------------
__global__ void zerofill(float* __restrict__ out)
{
    int r = blockIdx.x, b = r / T, t = r - b * T;
    if (t < d_dlen[b]) return;
    float4* p = (float4*)(out + (size_t)r * V);
    float4 z = make_float4(0.f, 0.f, 0.f, 0.f);
    for (int i = threadIdx.x; i < V / 4; i += blockDim.x) p[i] = z;
}

// ---------------------------------------------------------------------------
// persistent LSTM: round-9 proven structure + ONE change: register
// double-buffer on the h-chunk loads (prefetch k+1 after storing k, so the
// ~300cyc L2 latency overlaps the FMA loop instead of serializing).
// ---------------------------------------------------------------------------
__global__ __launch_bounds__(256) void lstm_persist(const float* __restrict__ w_hh)
{
    __shared__ float w_s[512][16];
    __shared__ __align__(16) float hs[16][132];
    __shared__ float c_s[512];
    __shared__ int s_start[NB];
    __shared__ int s_nt[T];

    int tid = threadIdx.x, d0 = blockIdx.x * 4;
    int tx = tid & 15, ty = tid >> 4;

    #pragma unroll
    for (int s = 0; s < 8; s++) {
        int lin = tid + s * 256;
        int i = lin >> 7, q = lin & 127;
        int gc = (i >> 2) * 512 + d0 + (i & 3);
        float4 v = __ldg((const float4*)(w_hh + (size_t)gc * 512 + q * 4));
        w_s[q*4+0][i]=v.x; w_s[q*4+1][i]=v.y; w_s[q*4+2][i]=v.z; w_s[q*4+3][i]=v.w;
    }
    if (tid < NB) s_start[tid] = d_start[tid];
    if (tid < T)  s_nt[tid] = d_nt[tid];
    for (int e = tid; e < 512; e += 256) c_s[e] = 0.f;
    __syncthreads();

    int row0 = tid >> 2, q2 = tid & 3;   // load-job rows (two per thread)
    int row1 = row0 + 64;

    for (int t = 0; t < T; t++) {
        int nt = s_nt[t];
        int nt8 = (nt + 7) & ~7;
        bool rowok = (ty * 8) < nt8;
        bool l0 = row0 < nt8, l1 = row1 < nt8;
        const float* hc = (t & 1) ? d_hB : d_hA;
        float*       hw = (t & 1) ? d_hA : d_hB;

        unsigned long long acc[4] = {0ull, 0ull, 0ull, 0ull};

        float4 v0, v1;                    // prefetch chunk 0
        if (l0) v0 = __ldcg((const float4*)(hc + (size_t)row0 * 512 + q2 * 4));
        if (l1) v1 = __ldcg((const float4*)(hc + (size_t)row1 * 512 + q2 * 4));

        for (int kc = 0; kc < 32; kc++) {
            if (l0) { hs[q2*4+0][row0]=v0.x; hs[q2*4+1][row0]=v0.y; hs[q2*4+2][row0]=v0.z; hs[q2*4+3][row0]=v0.w; }
            if (l1) { hs[q2*4+0][row1]=v1.x; hs[q2*4+1][row1]=v1.y; hs[q2*4+2][row1]=v1.z; hs[q2*4+3][row1]=v1.w; }
            __syncthreads();
            if (kc + 1 < 32) {            // prefetch next chunk, overlaps FMA
                int ko = (kc + 1) * 16 + q2 * 4;
                if (l0) v0 = __ldcg((const float4*)(hc + (size_t)row0 * 512 + ko));
                if (l1) v1 = __ldcg((const float4*)(hc + (size_t)row1 * 512 + ko));
            }
            if (rowok) {
                #pragma unroll
                for (int k = 0; k < 16; k++) {
                    ulonglong2 h01 = *(const ulonglong2*)&hs[k][ty * 8];
                    ulonglong2 h23 = *(const ulonglong2*)&hs[k][ty * 8 + 4];
                    unsigned long long wd = dup2(w_s[kc * 16 + k][tx]);
                    fma2(acc[0], h01.x, wd);
                    fma2(acc[1], h01.y, wd);
                    fma2(acc[2], h23.x, wd);
                    fma2(acc[3], h23.y, wd);
                }
            }
            __syncthreads();
        }
        #pragma unroll
        for (int p = 0; p < 4; p++) {
            float2 f = unpk(acc[p]);
            hs[tx][ty * 8 + p * 2 + 0] = f.x;
            hs[tx][ty * 8 + p * 2 + 1] = f.y;
        }
        __syncthreads();
        for (int e = tid; e < 512; e += 256) {
            int b = e >> 2, dd = e & 3;
            if (b < nt) {
                size_t cidx = (size_t)(s_start[b] + t);
                const float* xp = d_xproj + cidx * G + d0 + dd;
                float g0 = hs[dd][b]      + __ldg(xp);
                float g1 = hs[4 + dd][b]  + __ldg(xp + 512);
                float g2 = hs[8 + dd][b]  + __ldg(xp + 1024);
                float g3 = hs[12 + dd][b] + __ldg(xp + 1536);
                float gi = 1.f / (1.f + __expf(-g0));
                float gf = 1.f / (1.f + __expf(-g1));
                float gg = tanhf(g2);
                float go = 1.f / (1.f + __expf(-g3));
                float c  = c_s[e];
                float cn = gf * c + gi * gg;
                float hn = go * tanhf(cn);
                c_s[e] = cn;
                __stcg(hw + (size_t)b * 512 + d0 + dd, hn);
                d_Hbuf[cidx * 512 + d0 + dd] = hn;
            }
        }
        if (t < T - 1) {
            unsigned int target = (unsigned int)(t + 1) * (unsigned int)gridDim.x;
            __syncthreads();
            if (tid == 0) {
                __threadfence();
                atomicAdd(&d_ctr, 1u);
                while (*(volatile unsigned int*)&d_ctr < target) __nanosleep(32);
                __threadfence();
            }
            __syncthreads();
        }
    }
}

// ---------------------------------------------------------------------------
extern "C" void kernel_launch(void* const* d_in, const int* in_sizes, int n_in,
                              void* d_out, int out_size)
{
    const float* feats  = (const float*)d_in[0];
    const int*   caps   = (const int*)  d_in[1];
    const int*   clen   = (const int*)  d_in[2];
    const float* emb    = (const float*)d_in[3];
    const float* att1_w = (const float*)d_in[4];
    const float* att1_b = (const float*)d_in[5];
    const float* w_ih   = (const float*)d_in[6];
    const float* w_hh   = (const float*)d_in[7];
    const float* b_ih   = (const float*)d_in[8];
    const float* b_hh   = (const float*)d_in[9];
    const float* word_w = (const float*)d_in[10];
    const float* word_b = (const float*)d_in[11];
    float* out = (float*)d_out;

    float *xproj, *Hbuf, *bias2;
    int *tok, *vrow, *Sp;
    cudaGetSymbolAddress((void**)&xproj, d_xproj);
    cudaGetSymbolAddress((void**)&Hbuf,  d_Hbuf);
    cudaGetSymbolAddress((void**)&bias2, d_bias2);
    cudaGetSymbolAddress((void**)&tok,   d_tok);
    cudaGetSymbolAddress((void**)&vrow,  d_vrow);
    cudaGetSymbolAddress((void**)&Sp,    d_S);

    const long long PRED = (long long)NB * T * V;
    int write_tail = ((long long)out_size >= PRED + NB * L + 2 * NB) ? 1 : 0;

    prep_kernel<<<1, NB>>>(clen, caps, b_ih, b_hh, out, write_tail);
    mean_kernel<<<NB, 256>>>(feats);
    h0_kernel<<<dim3(NB, 4), 256>>>(att1_w, att1_b);

    // xproj (compacted rows): emb[tok] @ w_ih^T + (b_ih+b_hh)
    gemm128<true, false><<<dim3(R / 128, G / 128), 256>>>(
        emb, E, tok, w_ih, bias2, xproj, G, nullptr, Sp, G, E);

    zerofill<<<R, 256>>>(out);

    lstm_persist<<<NB, 256>>>(w_hh);

    // word projection: tf32 tensor cores, compacted rows, scatter to out
    word_mma<<<dim3((R + 63) / 64, (V + 63) / 64), 256>>>(
        Hbuf, word_w, word_b, out, vrow, Sp);
}

// round 11
// speedup vs baseline: 3.1940x; 1.0025x over previous
#include <cuda_runtime.h>
#include <math.h>

constexpr int NB=128, NP=196, FEAT=2048, E=512, D=512, V=10000, L=52, T=51;
constexpr int G=2048, R=NB*T;

__device__ float d_fm[NB*FEAT];
__device__ float d_hA[NB*D];
__device__ float d_hB[NB*D];
__device__ float d_xproj[(size_t)R*G];
__device__ float d_Hbuf[(size_t)R*D];
__device__ int d_sortind[NB], d_dlen[NB], d_start[NB], d_nt[T];
__device__ int d_S;
__device__ int d_tok[R], d_vrow[R];
__device__ float d_bias2[G];
__device__ volatile int d_flags2[NB];   // per-block arrival flags (reset by prep)
__device__ volatile int d_gen2;         // release word (reset by prep)

__device__ __forceinline__ void fma2(unsigned long long &d,
                                     unsigned long long a, unsigned long long b){
    asm("fma.rn.f32x2 %0, %1, %2, %0;" : "+l"(d) : "l"(a), "l"(b));
}
__device__ __forceinline__ unsigned long long dup2(float v){
    unsigned long long r; asm("mov.b64 %0, {%1, %1};" : "=l"(r) : "f"(v)); return r;
}
__device__ __forceinline__ float2 unpk(unsigned long long v){
    float2 f; asm("mov.b64 {%0, %1}, %2;" : "=f"(f.x), "=f"(f.y) : "l"(v)); return f;
}
__device__ __forceinline__ unsigned tf32_of(float f){
    unsigned u; asm("cvt.rna.tf32.f32 %0, %1;" : "=r"(u) : "f"(f)); return u;
}
__device__ __forceinline__ void mma_tf32(float* c, const unsigned* a, const unsigned* b){
    asm("mma.sync.aligned.m16n8k8.row.col.f32.tf32.tf32.f32 "
        "{%0,%1,%2,%3}, {%4,%5,%6,%7}, {%8,%9}, {%0,%1,%2,%3};"
        : "+f"(c[0]),"+f"(c[1]),"+f"(c[2]),"+f"(c[3])
        : "r"(a[0]),"r"(a[1]),"r"(a[2]),"r"(a[3]),"r"(b[0]),"r"(b[1]));
}

// ---------------------------------------------------------------------------
__global__ void prep_kernel(const int* __restrict__ clen,
                            const int* __restrict__ caps,
                            const float* __restrict__ b_ih,
                            const float* __restrict__ b_hh,
                            float* __restrict__ out, int write_tail)
{
    __shared__ int s_len[NB], s_dl[NB];
    int tid = threadIdx.x;
    if (tid == 0) d_gen2 = 0;
    d_flags2[tid] = 0;
    s_len[tid] = clen[tid];
    __syncthreads();
    int li = s_len[tid], rank = 0;
    for (int j = 0; j < NB; j++) {
        int lj = s_len[j];
        rank += (lj > li) || (lj == li && j < tid);
    }
    d_sortind[rank] = tid;
    __syncthreads();
    int src = d_sortind[tid];
    int dl  = s_len[src] - 1;
    d_dlen[tid] = dl;
    s_dl[tid] = dl;
    for (int r = tid; r < R; r += NB) { d_vrow[r] = 0; d_tok[r] = 0; }
    __syncthreads();
    if (tid < T) {
        int c = 0;
        for (int b = 0; b < NB; b++) c += (s_dl[b] > tid);
        d_nt[tid] = c;
    }
    int st = 0;
    for (int j = 0; j < tid; j++) st += s_dl[j];
    d_start[tid] = st;
    if (tid == NB - 1) d_S = st + dl;
    for (int t = 0; t < dl; t++) {
        d_vrow[st + t] = tid * T + t;
        d_tok[st + t]  = caps[src * L + t];
    }
    if (write_tail) {
        float* out_caps = out + (size_t)NB * T * V;
        float* out_dlen = out_caps + (size_t)NB * L;
        float* out_sort = out_dlen + NB;
        out_dlen[tid] = (float)dl;
        out_sort[tid] = (float)src;
        for (int j = 0; j < L; j++)
            out_caps[tid * L + j] = (float)caps[src * L + j];
    }
    for (int j = tid; j < G; j += NB) d_bias2[j] = b_ih[j] + b_hh[j];
}

// ---------------------------------------------------------------------------
__global__ void mean_kernel(const float* __restrict__ feats)
{
    int b = blockIdx.x, src = d_sortind[b], tid = threadIdx.x;
    const float* base = feats + (size_t)src * NP * FEAT;
    float acc[FEAT / 256];
    #pragma unroll
    for (int j = 0; j < FEAT / 256; j++) acc[j] = 0.f;
    for (int p = 0; p < NP; p++) {
        const float* row = base + (size_t)p * FEAT;
        #pragma unroll
        for (int j = 0; j < FEAT / 256; j++) acc[j] += __ldg(&row[tid + j * 256]);
    }
    #pragma unroll
    for (int j = 0; j < FEAT / 256; j++)
        d_fm[b * FEAT + tid + j * 256] = acc[j] * (1.f / NP);
}

// ---------------------------------------------------------------------------
__global__ void h0_kernel(const float* __restrict__ att1_w,
                          const float* __restrict__ att1_b)
{
    __shared__ float s_fm[FEAT];
    int b = blockIdx.x, c0 = blockIdx.y * 128;
    for (int i = threadIdx.x; i < FEAT; i += 256) s_fm[i] = d_fm[b * FEAT + i];
    __syncthreads();
    int warp = threadIdx.x >> 5, lane = threadIdx.x & 31;
    for (int cc = warp; cc < 128; cc += 8) {
        int col = c0 + cc;
        const float4* wr = (const float4*)(att1_w + (size_t)col * FEAT);
        float s = 0.f;
        for (int k = lane; k < FEAT / 4; k += 32) {
            float4 w = __ldg(&wr[k]);
            float4 f = *(const float4*)&s_fm[k * 4];
            s += w.x * f.x + w.y * f.y + w.z * f.z + w.w * f.w;
        }
        #pragma unroll
        for (int o = 16; o; o >>= 1) s += __shfl_down_sync(~0u, s, o);
        if (!lane) d_hA[b * D + col] = s + __ldg(&att1_b[col]);
    }
}

// ---------------------------------------------------------------------------
// fp32 f32x2 GEMM (used for xproj). Proven in rounds 5/7/9/10.
// ---------------------------------------------------------------------------
template<bool GA, bool SCAT>
__global__ __launch_bounds__(256, 2) void gemm128(
    const float* __restrict__ A, int lda, const int* __restrict__ aIdx,
    const float* __restrict__ Bm, const float* __restrict__ bias,
    float* __restrict__ Cout, int ldc, const int* __restrict__ outIdx,
    const int* __restrict__ MvP, int N, int K)
{
    __shared__ __align__(16) float As[2][16][132];
    __shared__ __align__(16) float Bs[2][16][132];
    __shared__ int s_src[128];

    int m0 = blockIdx.x * 128, n0 = blockIdx.y * 128;
    int Mv = MvP ? __ldg(MvP) : 0x7fffffff;
    if (m0 >= Mv) return;

    int tid = threadIdx.x;
    if (tid < 128) s_src[tid] = GA ? __ldg(&aIdx[m0 + tid]) : (m0 + tid);
    __syncthreads();

    int tx = tid & 15, ty = tid >> 4;
    int tx4 = tx * 4, ty4 = ty * 4;
    int j1 = tid + 256;
    int r0 = tid >> 2, q0 = tid & 3;
    int r1 = j1 >> 2,  q1 = j1 & 3;
    const float* Ar0 = A + (size_t)s_src[r0] * lda + q0 * 4;
    const float* Ar1 = A + (size_t)s_src[r1] * lda + q1 * 4;
    bool bok0 = (n0 + r0) < N, bok1 = (n0 + r1) < N;
    const float* Br0 = Bm + (size_t)(n0 + r0) * K + q0 * 4;
    const float* Br1 = Bm + (size_t)(n0 + r1) * K + q1 * 4;
    const float4 z4 = make_float4(0.f, 0.f, 0.f, 0.f);

    unsigned long long acc[4][8];
    #pragma unroll
    for (int p = 0; p < 4; p++)
        #pragma unroll
        for (int j = 0; j < 8; j++) acc[p][j] = 0ull;

    float4 ra0 = __ldg((const float4*)Ar0);
    float4 ra1 = __ldg((const float4*)Ar1);
    float4 rb0 = bok0 ? __ldg((const float4*)Br0) : z4;
    float4 rb1 = bok1 ? __ldg((const float4*)Br1) : z4;
    As[0][q0*4+0][r0]=ra0.x; As[0][q0*4+1][r0]=ra0.y; As[0][q0*4+2][r0]=ra0.z; As[0][q0*4+3][r0]=ra0.w;
    As[0][q1*4+0][r1]=ra1.x; As[0][q1*4+1][r1]=ra1.y; As[0][q1*4+2][r1]=ra1.z; As[0][q1*4+3][r1]=ra1.w;
    Bs[0][q0*4+0][r0]=rb0.x; Bs[0][q0*4+1][r0]=rb0.y; Bs[0][q0*4+2][r0]=rb0.z; Bs[0][q0*4+3][r0]=rb0.w;
    Bs[0][q1*4+0][r1]=rb1.x; Bs[0][q1*4+1][r1]=rb1.y; Bs[0][q1*4+2][r1]=rb1.z; Bs[0][q1*4+3][r1]=rb1.w;
    __syncthreads();

    const int KT = K / 16;
    for (int kt = 0; kt < KT; kt++) {
        int cur = kt & 1;
        if (kt + 1 < KT) {
            int ko = (kt + 1) * 16;
            ra0 = __ldg((const float4*)(Ar0 + ko));
            ra1 = __ldg((const float4*)(Ar1 + ko));
            rb0 = bok0 ? __ldg((const float4*)(Br0 + ko)) : z4;
            rb1 = bok1 ? __ldg((const float4*)(Br1 + ko)) : z4;
        }
        #pragma unroll
        for (int k = 0; k < 16; k++) {
            ulonglong2 a01 = *(const ulonglong2*)&As[cur][k][ty4];
            ulonglong2 a23 = *(const ulonglong2*)&As[cur][k][ty4 + 64];
            float4 b0 = *(const float4*)&Bs[cur][k][tx4];
            float4 b1 = *(const float4*)&Bs[cur][k][tx4 + 64];
            unsigned long long pa[4] = {a01.x, a01.y, a23.x, a23.y};
            unsigned long long pb[8] = {dup2(b0.x), dup2(b0.y), dup2(b0.z), dup2(b0.w),
                                        dup2(b1.x), dup2(b1.y), dup2(b1.z), dup2(b1.w)};
            #pragma unroll
            for (int p = 0; p < 4; p++)
                #pragma unroll
                for (int j = 0; j < 8; j++)
                    fma2(acc[p][j], pa[p], pb[j]);
        }
        if (kt + 1 < KT) {
            int nb = 1 - cur;
            As[nb][q0*4+0][r0]=ra0.x; As[nb][q0*4+1][r0]=ra0.y; As[nb][q0*4+2][r0]=ra0.z; As[nb][q0*4+3][r0]=ra0.w;
            As[nb][q1*4+0][r1]=ra1.x; As[nb][q1*4+1][r1]=ra1.y; As[nb][q1*4+2][r1]=ra1.z; As[nb][q1*4+3][r1]=ra1.w;
            Bs[nb][q0*4+0][r0]=rb0.x; Bs[nb][q0*4+1][r0]=rb0.y; Bs[nb][q0*4+2][r0]=rb0.z; Bs[nb][q0*4+3][r0]=rb0.w;
            Bs[nb][q1*4+0][r1]=rb1.x; Bs[nb][q1*4+1][r1]=rb1.y; Bs[nb][q1*4+2][r1]=rb1.z; Bs[nb][q1*4+3][r1]=rb1.w;
        }
        __syncthreads();
    }

    bool cok0 = (n0 + tx4) < N, cok1 = (n0 + tx4 + 64) < N;
    float4 bi0 = z4, bi1 = z4;
    if (bias) {
        if (cok0) bi0 = __ldg((const float4*)(bias + n0 + tx4));
        if (cok1) bi1 = __ldg((const float4*)(bias + n0 + tx4 + 64));
    }
    #pragma unroll
    for (int p = 0; p < 4; p++) {
        int rbase = m0 + ((p < 2) ? (ty4 + 2 * p) : (64 + ty4 + 2 * (p - 2)));
        float2 u[8];
        #pragma unroll
        for (int j = 0; j < 8; j++) u[j] = unpk(acc[p][j]);
        float4 lo0 = make_float4(u[0].x+bi0.x, u[1].x+bi0.y, u[2].x+bi0.z, u[3].x+bi0.w);
        float4 lo1 = make_float4(u[4].x+bi1.x, u[5].x+bi1.y, u[6].x+bi1.z, u[7].x+bi1.w);
        float4 hi0 = make_float4(u[0].y+bi0.x, u[1].y+bi0.y, u[2].y+bi0.z, u[3].y+bi0.w);
        float4 hi1 = make_float4(u[4].y+bi1.x, u[5].y+bi1.y, u[6].y+bi1.z, u[7].y+bi1.w);
        if (!SCAT || rbase < Mv) {
            size_t orow = SCAT ? (size_t)__ldg(&outIdx[rbase]) : (size_t)rbase;
            if (cok0) *(float4*)(Cout + orow * ldc + n0 + tx4)      = lo0;
            if (cok1) *(float4*)(Cout + orow * ldc + n0 + tx4 + 64) = lo1;
        }
        int rh = rbase + 1;
        if (!SCAT || rh < Mv) {
            size_t orow = SCAT ? (size_t)__ldg(&outIdx[rh]) : (size_t)rh;
            if (cok0) *(float4*)(Cout + orow * ldc + n0 + tx4)      = hi0;
            if (cok1) *(float4*)(Cout + orow * ldc + n0 + tx4 + 64) = hi1;
        }
    }
}

// ---------------------------------------------------------------------------
// tf32 word projection v3: 128x128 tiles, k-chunk 16, row stride ST=20
// (g*20 mod 32 distinct for g<8 -> conflict-free frag gather), STS.128
// stores, double-buffered smem (40KB), register prefetch.
// 8 warps as 4m x 2n; each warp: m 32 x n 64 -> acc[2][8][4].
// Same k-summation order as v2 => identical numerics.
// ---------------------------------------------------------------------------
__global__ __launch_bounds__(256) void word_mma(
    const float* __restrict__ A,       // Hbuf [R][512]
    const float* __restrict__ Bm,      // word_w [V][512]
    const float* __restrict__ bias,    // word_b [V]
    float* __restrict__ Cout,          // out [R][V]
    const int* __restrict__ outIdx,    // vrow
    const int* __restrict__ MvP)       // d_S
{
    constexpr int ST = 20;                          // words per smem row
    __shared__ __align__(16) unsigned As[2][128 * ST];
    __shared__ __align__(16) unsigned Bs[2][128 * ST];

    int m0 = blockIdx.x * 128, n0 = blockIdx.y * 128;
    int Mv = __ldg(MvP);
    if (m0 >= Mv) return;

    int tid = threadIdx.x, lane = tid & 31, w = tid >> 5;
    int wm = w & 3, wn = w >> 2;        // 4m x 2n warp grid
    int lrow = tid >> 2, q = tid & 3;   // rows lrow & lrow+64, float4 slot q
    const float4 z4 = make_float4(0.f, 0.f, 0.f, 0.f);

    const float4* Ag0 = (const float4*)(A + (size_t)(m0 + lrow)      * D) + q;
    const float4* Ag1 = (const float4*)(A + (size_t)(m0 + lrow + 64) * D) + q;
    int br0 = n0 + lrow, br1 = n0 + lrow + 64;
    bool bok0 = br0 < V, bok1 = br1 < V;
    const float4* Bg0 = (const float4*)(Bm + (size_t)(bok0 ? br0 : 0) * D) + q;
    const float4* Bg1 = (const float4*)(Bm + (size_t)(bok1 ? br1 : 0) * D) + q;

    int s0 = lrow * ST + q * 4;         // 16B aligned (20 ≡ 0 mod 4)
    int s1 = (lrow + 64) * ST + q * 4;

    float acc[2][8][4];
    #pragma unroll
    for (int i = 0; i < 2; i++)
        #pragma unroll
        for (int j = 0; j < 8; j++)
            #pragma unroll
            for (int r = 0; r < 4; r++) acc[i][j][r] = 0.f;

    float4 pa0 = __ldg(Ag0), pa1 = __ldg(Ag1);
    float4 pb0 = bok0 ? __ldg(Bg0) : z4;
    float4 pb1 = bok1 ? __ldg(Bg1) : z4;
    {
        uint4 u;
        u.x=tf32_of(pa0.x); u.y=tf32_of(pa0.y); u.z=tf32_of(pa0.z); u.w=tf32_of(pa0.w);
        *(uint4*)&As[0][s0] = u;
        u.x=tf32_of(pa1.x); u.y=tf32_of(pa1.y); u.z=tf32_of(pa1.z); u.w=tf32_of(pa1.w);
        *(uint4*)&As[0][s1] = u;
        u.x=tf32_of(pb0.x); u.y=tf32_of(pb0.y); u.z=tf32_of(pb0.z); u.w=tf32_of(pb0.w);
        *(uint4*)&Bs[0][s0] = u;
        u.x=tf32_of(pb1.x); u.y=tf32_of(pb1.y); u.z=tf32_of(pb1.z); u.w=tf32_of(pb1.w);
        *(uint4*)&Bs[0][s1] = u;
    }
    __syncthreads();

    int g = lane >> 2, t4 = lane & 3;
    const int KT = D / 16;   // 32 chunks of k=16
    for (int kt = 0; kt < KT; kt++) {
        int cur = kt & 1;
        if (kt + 1 < KT) {
            int ko = (kt + 1) * 4;               // float4 units per row
            pa0 = __ldg(Ag0 + ko); pa1 = __ldg(Ag1 + ko);
            pb0 = bok0 ? __ldg(Bg0 + ko) : z4;
            pb1 = bok1 ? __ldg(Bg1 + ko) : z4;
        }
        #pragma unroll
        for (int ks = 0; ks < 2; ks++) {
            int kb = ks * 8;
            unsigned af[2][4], bf[8][2];
            #pragma unroll
            for (int i = 0; i < 2; i++) {
                int base = (wm * 32 + i * 16 + g) * ST + kb + t4;
                af[i][0] = As[cur][base];
                af[i][1] = As[cur][base + 8 * ST];
                af[i][2] = As[cur][base + 4];
                af[i][3] = As[cur][base + 8 * ST + 4];
            }
            #pragma unroll
            for (int j = 0; j < 8; j++) {
                int base = (wn * 64 + j * 8 + g) * ST + kb + t4;
                bf[j][0] = Bs[cur][base];
                bf[j][1] = Bs[cur][base + 4];
            }
            #pragma unroll
            for (int i = 0; i < 2; i++)
                #pragma unroll
                for (int j = 0; j < 8; j++)
                    mma_tf32(acc[i][j], af[i], bf[j]);
        }
        if (kt + 1 < KT) {
            int nb = 1 - cur;
            uint4 u;
            u.x=tf32_of(pa0.x); u.y=tf32_of(pa0.y); u.z=tf32_of(pa0.z); u.w=tf32_of(pa0.w);
            *(uint4*)&As[nb][s0] = u;
            u.x=tf32_of(pa1.x); u.y=tf32_of(pa1.y); u.z=tf32_of(pa1.z); u.w=tf32_of(pa1.w);
            *(uint4*)&As[nb][s1] = u;
            u.x=tf32_of(pb0.x); u.y=tf32_of(pb0.y); u.z=tf32_of(pb0.z); u.w=tf32_of(pb0.w);
            *(uint4*)&Bs[nb][s0] = u;
            u.x=tf32_of(pb1.x); u.y=tf32_of(pb1.y); u.z=tf32_of(pb1.z); u.w=tf32_of(pb1.w);
            *(uint4*)&Bs[nb][s1] = u;
        }
        __syncthreads();
    }

    int r0 = lane >> 2, tg = lane & 3;
    #pragma unroll
    for (int i = 0; i < 2; i++) {
        #pragma unroll
        for (int h = 0; h < 2; h++) {
            int gr = m0 + wm * 32 + i * 16 + r0 + h * 8;
            if (gr < Mv) {
                size_t orow = (size_t)__ldg(&outIdx[gr]);
                float* outr = Cout + orow * V;
                #pragma unroll
                for (int j = 0; j < 8; j++) {
                    int gc = n0 + wn * 64 + j * 8 + tg * 2;
                    if (gc < V) {
                        float b0 = __ldg(&bias[gc]), b1 = __ldg(&bias[gc + 1]);
                        float2 v;
                        v.x = acc[i][j][h * 2 + 0] + b0;
                        v.y = acc[i][j][h * 2 + 1] + b1;
                        *(float2*)(outr + gc) = v;
                    }
                }
            }
        }
    }
}

// ---------------------------------------------------------------------------
__global__ void zerofill(float* __restrict__ out)
{
    int r = blockIdx.x, b = r / T, t = r - b * T;
    if (t < d_dlen[b]) return;
    float4* p = (float4*)(out + (size_t)r * V);
    float4 z = make_float4(0.f, 0.f, 0.f, 0.f);
    for (int i = threadIdx.x; i < V / 4; i += blockDim.x) p[i] = z;
}

// ---------------------------------------------------------------------------
// persistent LSTM: round-10 proven (register-prefetch) version; only the
// grid barrier changed: distributed flags + broadcast release instead of
// 128 serialized atomics on one address.
// ---------------------------------------------------------------------------
__global__ __launch_bounds__(256) void lstm_persist(const float* __restrict__ w_hh)
{
    __shared__ float w_s[512][16];
    __shared__ __align__(16) float hs[16][132];
    __shared__ float c_s[512];
    __shared__ int s_start[NB];
    __shared__ int s_nt[T];

    int tid = threadIdx.x, d0 = blockIdx.x * 4;
    int tx = tid & 15, ty = tid >> 4;

    #pragma unroll
    for (int s = 0; s < 8; s++) {
        int lin = tid + s * 256;
        int i = lin >> 7, q = lin & 127;
        int gc = (i >> 2) * 512 + d0 + (i & 3);
        float4 v = __ldg((const float4*)(w_hh + (size_t)gc * 512 + q * 4));
        w_s[q*4+0][i]=v.x; w_s[q*4+1][i]=v.y; w_s[q*4+2][i]=v.z; w_s[q*4+3][i]=v.w;
    }
    if (tid < NB) s_start[tid] = d_start[tid];
    if (tid < T)  s_nt[tid] = d_nt[tid];
    for (int e = tid; e < 512; e += 256) c_s[e] = 0.f;
    __syncthreads();

    int row0 = tid >> 2, q2 = tid & 3;
    int row1 = row0 + 64;

    for (int t = 0; t < T; t++) {
        int nt = s_nt[t];
        int nt8 = (nt + 7) & ~7;
        bool rowok = (ty * 8) < nt8;
        bool l0 = row0 < nt8, l1 = row1 < nt8;
        const float* hc = (t & 1) ? d_hB : d_hA;
        float*       hw = (t & 1) ? d_hA : d_hB;

        unsigned long long acc[4] = {0ull, 0ull, 0ull, 0ull};

        float4 v0, v1;
        if (l0) v0 = __ldcg((const float4*)(hc + (size_t)row0 * 512 + q2 * 4));
        if (l1) v1 = __ldcg((const float4*)(hc + (size_t)row1 * 512 + q2 * 4));

        for (int kc = 0; kc < 32; kc++) {
            if (l0) { hs[q2*4+0][row0]=v0.x; hs[q2*4+1][row0]=v0.y; hs[q2*4+2][row0]=v0.z; hs[q2*4+3][row0]=v0.w; }
            if (l1) { hs[q2*4+0][row1]=v1.x; hs[q2*4+1][row1]=v1.y; hs[q2*4+2][row1]=v1.z; hs[q2*4+3][row1]=v1.w; }
            __syncthreads();
            if (kc + 1 < 32) {
                int ko = (kc + 1) * 16 + q2 * 4;
                if (l0) v0 = __ldcg((const float4*)(hc + (size_t)row0 * 512 + ko));
                if (l1) v1 = __ldcg((const float4*)(hc + (size_t)row1 * 512 + ko));
            }
            if (rowok) {
                #pragma unroll
                for (int k = 0; k < 16; k++) {
                    ulonglong2 h01 = *(const ulonglong2*)&hs[k][ty * 8];
                    ulonglong2 h23 = *(const ulonglong2*)&hs[k][ty * 8 + 4];
                    unsigned long long wd = dup2(w_s[kc * 16 + k][tx]);
                    fma2(acc[0], h01.x, wd);
                    fma2(acc[1], h01.y, wd);
                    fma2(acc[2], h23.x, wd);
                    fma2(acc[3], h23.y, wd);
                }
            }
            __syncthreads();
        }
        #pragma unroll
        for (int p = 0; p < 4; p++) {
            float2 f = unpk(acc[p]);
            hs[tx][ty * 8 + p * 2 + 0] = f.x;
            hs[tx][ty * 8 + p * 2 + 1] = f.y;
        }
        __syncthreads();
        for (int e = tid; e < 512; e += 256) {
            int b = e >> 2, dd = e & 3;
            if (b < nt) {
                size_t cidx = (size_t)(s_start[b] + t);
                const float* xp = d_xproj + cidx * G + d0 + dd;
                float g0 = hs[dd][b]      + __ldg(xp);
                float g1 = hs[4 + dd][b]  + __ldg(xp + 512);
                float g2 = hs[8 + dd][b]  + __ldg(xp + 1024);
                float g3 = hs[12 + dd][b] + __ldg(xp + 1536);
                float gi = 1.f / (1.f + __expf(-g0));
                float gf = 1.f / (1.f + __expf(-g1));
                float gg = tanhf(g2);
                float go = 1.f / (1.f + __expf(-g3));
                float c  = c_s[e];
                float cn = gf * c + gi * gg;
                float hn = go * tanhf(cn);
                c_s[e] = cn;
                __stcg(hw + (size_t)b * 512 + d0 + dd, hn);
                d_Hbuf[cidx * 512 + d0 + dd] = hn;
            }
        }
        // ---- grid barrier: distributed flags (reset by prep each launch) ----
        if (t < T - 1) {
            int tg2 = t + 1;
            __syncthreads();
            if (tid == 0) { __threadfence(); d_flags2[blockIdx.x] = tg2; }
            if (blockIdx.x == 0) {
                if (tid < NB) { while (d_flags2[tid] < tg2) __nanosleep(32); }
                __syncthreads();
                if (tid == 0) { __threadfence(); d_gen2 = tg2; }
            }
            if (tid == 0) { while (d_gen2 < tg2) __nanosleep(32); __threadfence(); }
            __syncthreads();
        }
    }
}

// ---------------------------------------------------------------------------
extern "C" void kernel_launch(void* const* d_in, const int* in_sizes, int n_in,
                              void* d_out, int out_size)
{
    const float* feats  = (const float*)d_in[0];
    const int*   caps   = (const int*)  d_in[1];
    const int*   clen   = (const int*)  d_in[2];
    const float* emb    = (const float*)d_in[3];
    const float* att1_w = (const float*)d_in[4];
    const float* att1_b = (const float*)d_in[5];
    const float* w_ih   = (const float*)d_in[6];
    const float* w_hh   = (const float*)d_in[7];
    const float* b_ih   = (const float*)d_in[8];
    const float* b_hh   = (const float*)d_in[9];
    const float* word_w = (const float*)d_in[10];
    const float* word_b = (const float*)d_in[11];
    float* out = (float*)d_out;

    float *xproj, *Hbuf, *bias2;
    int *tok, *vrow, *Sp;
    cudaGetSymbolAddress((void**)&xproj, d_xproj);
    cudaGetSymbolAddress((void**)&Hbuf,  d_Hbuf);
    cudaGetSymbolAddress((void**)&bias2, d_bias2);
    cudaGetSymbolAddress((void**)&tok,   d_tok);
    cudaGetSymbolAddress((void**)&vrow,  d_vrow);
    cudaGetSymbolAddress((void**)&Sp,    d_S);

    const long long PRED = (long long)NB * T * V;
    int write_tail = ((long long)out_size >= PRED + NB * L + 2 * NB) ? 1 : 0;

    prep_kernel<<<1, NB>>>(clen, caps, b_ih, b_hh, out, write_tail);
    mean_kernel<<<NB, 256>>>(feats);
    h0_kernel<<<dim3(NB, 4), 256>>>(att1_w, att1_b);

    // xproj (compacted rows): emb[tok] @ w_ih^T + (b_ih+b_hh)
    gemm128<true, false><<<dim3(R / 128, G / 128), 256>>>(
        emb, E, tok, w_ih, bias2, xproj, G, nullptr, Sp, G, E);

    zerofill<<<R, 256>>>(out);

    lstm_persist<<<NB, 256>>>(w_hh);

    // word projection: tf32 tensor cores, 128x128 tiles, scatter to out
    word_mma<<<dim3((R + 127) / 128, (V + 127) / 128), 256>>>(
        Hbuf, word_w, word_b, out, vrow, Sp);
}

// round 12
// speedup vs baseline: 3.2495x; 1.0174x over previous
#include <cuda_runtime.h>
#include <math.h>

constexpr int NB=128, NP=196, FEAT=2048, E=512, D=512, V=10000, L=52, T=51;
constexpr int G=2048, R=NB*T;

__device__ float d_fm[NB*FEAT];
__device__ float d_hA[NB*D];
__device__ float d_hB[NB*D];
__device__ float d_xproj[(size_t)R*G];
__device__ float d_Hbuf[(size_t)R*D];
__device__ int d_sortind[NB], d_dlen[NB], d_start[NB], d_nt[T];
__device__ int d_S;
__device__ int d_tok[R], d_vrow[R];
__device__ float d_bias2[G];
__device__ volatile int d_flags2[NB];   // per-block arrival flags (reset by prep)
__device__ volatile int d_gen2;         // release word (reset by prep)

__device__ __forceinline__ void fma2(unsigned long long &d,
                                     unsigned long long a, unsigned long long b){
    asm("fma.rn.f32x2 %0, %1, %2, %0;" : "+l"(d) : "l"(a), "l"(b));
}
__device__ __forceinline__ unsigned long long dup2(float v){
    unsigned long long r; asm("mov.b64 %0, {%1, %1};" : "=l"(r) : "f"(v)); return r;
}
__device__ __forceinline__ float2 unpk(unsigned long long v){
    float2 f; asm("mov.b64 {%0, %1}, %2;" : "=f"(f.x), "=f"(f.y) : "l"(v)); return f;
}
__device__ __forceinline__ unsigned tf32_of(float f){
    unsigned u; asm("cvt.rna.tf32.f32 %0, %1;" : "=r"(u) : "f"(f)); return u;
}
__device__ __forceinline__ void mma_tf32(float* c, const unsigned* a, const unsigned* b){
    asm("mma.sync.aligned.m16n8k8.row.col.f32.tf32.tf32.f32 "
        "{%0,%1,%2,%3}, {%4,%5,%6,%7}, {%8,%9}, {%0,%1,%2,%3};"
        : "+f"(c[0]),"+f"(c[1]),"+f"(c[2]),"+f"(c[3])
        : "r"(a[0]),"r"(a[1]),"r"(a[2]),"r"(a[3]),"r"(b[0]),"r"(b[1]));
}

// ---------------------------------------------------------------------------
__global__ void prep_kernel(const int* __restrict__ clen,
                            const int* __restrict__ caps,
                            const float* __restrict__ b_ih,
                            const float* __restrict__ b_hh,
                            float* __restrict__ out, int write_tail)
{
    __shared__ int s_len[NB], s_dl[NB];
    int tid = threadIdx.x;
    if (tid == 0) d_gen2 = 0;
    d_flags2[tid] = 0;
    s_len[tid] = clen[tid];
    __syncthreads();
    int li = s_len[tid], rank = 0;
    for (int j = 0; j < NB; j++) {
        int lj = s_len[j];
        rank += (lj > li) || (lj == li && j < tid);
    }
    d_sortind[rank] = tid;
    __syncthreads();
    int src = d_sortind[tid];
    int dl  = s_len[src] - 1;
    d_dlen[tid] = dl;
    s_dl[tid] = dl;
    for (int r = tid; r < R; r += NB) { d_vrow[r] = 0; d_tok[r] = 0; }
    __syncthreads();
    if (tid < T) {
        int c = 0;
        for (int b = 0; b < NB; b++) c += (s_dl[b] > tid);
        d_nt[tid] = c;
    }
    int st = 0;
    for (int j = 0; j < tid; j++) st += s_dl[j];
    d_start[tid] = st;
    if (tid == NB - 1) d_S = st + dl;
    for (int t = 0; t < dl; t++) {
        d_vrow[st + t] = tid * T + t;
        d_tok[st + t]  = caps[src * L + t];
    }
    if (write_tail) {
        float* out_caps = out + (size_t)NB * T * V;
        float* out_dlen = out_caps + (size_t)NB * L;
        float* out_sort = out_dlen + NB;
        out_dlen[tid] = (float)dl;
        out_sort[tid] = (float)src;
        for (int j = 0; j < L; j++)
            out_caps[tid * L + j] = (float)caps[src * L + j];
    }
    for (int j = tid; j < G; j += NB) d_bias2[j] = b_ih[j] + b_hh[j];
}

// ---------------------------------------------------------------------------
__global__ void mean_kernel(const float* __restrict__ feats)
{
    int b = blockIdx.x, src = d_sortind[b], tid = threadIdx.x;
    const float* base = feats + (size_t)src * NP * FEAT;
    float acc[FEAT / 256];
    #pragma unroll
    for (int j = 0; j < FEAT / 256; j++) acc[j] = 0.f;
    for (int p = 0; p < NP; p++) {
        const float* row = base + (size_t)p * FEAT;
        #pragma unroll
        for (int j = 0; j < FEAT / 256; j++) acc[j] += __ldg(&row[tid + j * 256]);
    }
    #pragma unroll
    for (int j = 0; j < FEAT / 256; j++)
        d_fm[b * FEAT + tid + j * 256] = acc[j] * (1.f / NP);
}

// ---------------------------------------------------------------------------
__global__ void h0_kernel(const float* __restrict__ att1_w,
                          const float* __restrict__ att1_b)
{
    __shared__ float s_fm[FEAT];
    int b = blockIdx.x, c0 = blockIdx.y * 128;
    for (int i = threadIdx.x; i < FEAT; i += 256) s_fm[i] = d_fm[b * FEAT + i];
    __syncthreads();
    int warp = threadIdx.x >> 5, lane = threadIdx.x & 31;
    for (int cc = warp; cc < 128; cc += 8) {
        int col = c0 + cc;
        const float4* wr = (const float4*)(att1_w + (size_t)col * FEAT);
        float s = 0.f;
        for (int k = lane; k < FEAT / 4; k += 32) {
            float4 w = __ldg(&wr[k]);
            float4 f = *(const float4*)&s_fm[k * 4];
            s += w.x * f.x + w.y * f.y + w.z * f.z + w.w * f.w;
        }
        #pragma unroll
        for (int o = 16; o; o >>= 1) s += __shfl_down_sync(~0u, s, o);
        if (!lane) d_hA[b * D + col] = s + __ldg(&att1_b[col]);
    }
}

// ---------------------------------------------------------------------------
// fp32 f32x2 GEMM (used for xproj). Proven rounds 5-11.
// ---------------------------------------------------------------------------
template<bool GA, bool SCAT>
__global__ __launch_bounds__(256, 2) void gemm128(
    const float* __restrict__ A, int lda, const int* __restrict__ aIdx,
    const float* __restrict__ Bm, const float* __restrict__ bias,
    float* __restrict__ Cout, int ldc, const int* __restrict__ outIdx,
    const int* __restrict__ MvP, int N, int K)
{
    __shared__ __align__(16) float As[2][16][132];
    __shared__ __align__(16) float Bs[2][16][132];
    __shared__ int s_src[128];

    int m0 = blockIdx.x * 128, n0 = blockIdx.y * 128;
    int Mv = MvP ? __ldg(MvP) : 0x7fffffff;
    if (m0 >= Mv) return;

    int tid = threadIdx.x;
    if (tid < 128) s_src[tid] = GA ? __ldg(&aIdx[m0 + tid]) : (m0 + tid);
    __syncthreads();

    int tx = tid & 15, ty = tid >> 4;
    int tx4 = tx * 4, ty4 = ty * 4;
    int j1 = tid + 256;
    int r0 = tid >> 2, q0 = tid & 3;
    int r1 = j1 >> 2,  q1 = j1 & 3;
    const float* Ar0 = A + (size_t)s_src[r0] * lda + q0 * 4;
    const float* Ar1 = A + (size_t)s_src[r1] * lda + q1 * 4;
    bool bok0 = (n0 + r0) < N, bok1 = (n0 + r1) < N;
    const float* Br0 = Bm + (size_t)(n0 + r0) * K + q0 * 4;
    const float* Br1 = Bm + (size_t)(n0 + r1) * K + q1 * 4;
    const float4 z4 = make_float4(0.f, 0.f, 0.f, 0.f);

    unsigned long long acc[4][8];
    #pragma unroll
    for (int p = 0; p < 4; p++)
        #pragma unroll
        for (int j = 0; j < 8; j++) acc[p][j] = 0ull;

    float4 ra0 = __ldg((const float4*)Ar0);
    float4 ra1 = __ldg((const float4*)Ar1);
    float4 rb0 = bok0 ? __ldg((const float4*)Br0) : z4;
    float4 rb1 = bok1 ? __ldg((const float4*)Br1) : z4;
    As[0][q0*4+0][r0]=ra0.x; As[0][q0*4+1][r0]=ra0.y; As[0][q0*4+2][r0]=ra0.z; As[0][q0*4+3][r0]=ra0.w;
    As[0][q1*4+0][r1]=ra1.x; As[0][q1*4+1][r1]=ra1.y; As[0][q1*4+2][r1]=ra1.z; As[0][q1*4+3][r1]=ra1.w;
    Bs[0][q0*4+0][r0]=rb0.x; Bs[0][q0*4+1][r0]=rb0.y; Bs[0][q0*4+2][r0]=rb0.z; Bs[0][q0*4+3][r0]=rb0.w;
    Bs[0][q1*4+0][r1]=rb1.x; Bs[0][q1*4+1][r1]=rb1.y; Bs[0][q1*4+2][r1]=rb1.z; Bs[0][q1*4+3][r1]=rb1.w;
    __syncthreads();

    const int KT = K / 16;
    for (int kt = 0; kt < KT; kt++) {
        int cur = kt & 1;
        if (kt + 1 < KT) {
            int ko = (kt + 1) * 16;
            ra0 = __ldg((const float4*)(Ar0 + ko));
            ra1 = __ldg((const float4*)(Ar1 + ko));
            rb0 = bok0 ? __ldg((const float4*)(Br0 + ko)) : z4;
            rb1 = bok1 ? __ldg((const float4*)(Br1 + ko)) : z4;
        }
        #pragma unroll
        for (int k = 0; k < 16; k++) {
            ulonglong2 a01 = *(const ulonglong2*)&As[cur][k][ty4];
            ulonglong2 a23 = *(const ulonglong2*)&As[cur][k][ty4 + 64];
            float4 b0 = *(const float4*)&Bs[cur][k][tx4];
            float4 b1 = *(const float4*)&Bs[cur][k][tx4 + 64];
            unsigned long long pa[4] = {a01.x, a01.y, a23.x, a23.y};
            unsigned long long pb[8] = {dup2(b0.x), dup2(b0.y), dup2(b0.z), dup2(b0.w),
                                        dup2(b1.x), dup2(b1.y), dup2(b1.z), dup2(b1.w)};
            #pragma unroll
            for (int p = 0; p < 4; p++)
                #pragma unroll
                for (int j = 0; j < 8; j++)
                    fma2(acc[p][j], pa[p], pb[j]);
        }
        if (kt + 1 < KT) {
            int nb = 1 - cur;
            As[nb][q0*4+0][r0]=ra0.x; As[nb][q0*4+1][r0]=ra0.y; As[nb][q0*4+2][r0]=ra0.z; As[nb][q0*4+3][r0]=ra0.w;
            As[nb][q1*4+0][r1]=ra1.x; As[nb][q1*4+1][r1]=ra1.y; As[nb][q1*4+2][r1]=ra1.z; As[nb][q1*4+3][r1]=ra1.w;
            Bs[nb][q0*4+0][r0]=rb0.x; Bs[nb][q0*4+1][r0]=rb0.y; Bs[nb][q0*4+2][r0]=rb0.z; Bs[nb][q0*4+3][r0]=rb0.w;
            Bs[nb][q1*4+0][r1]=rb1.x; Bs[nb][q1*4+1][r1]=rb1.y; Bs[nb][q1*4+2][r1]=rb1.z; Bs[nb][q1*4+3][r1]=rb1.w;
        }
        __syncthreads();
    }

    bool cok0 = (n0 + tx4) < N, cok1 = (n0 + tx4 + 64) < N;
    float4 bi0 = z4, bi1 = z4;
    if (bias) {
        if (cok0) bi0 = __ldg((const float4*)(bias + n0 + tx4));
        if (cok1) bi1 = __ldg((const float4*)(bias + n0 + tx4 + 64));
    }
    #pragma unroll
    for (int p = 0; p < 4; p++) {
        int rbase = m0 + ((p < 2) ? (ty4 + 2 * p) : (64 + ty4 + 2 * (p - 2)));
        float2 u[8];
        #pragma unroll
        for (int j = 0; j < 8; j++) u[j] = unpk(acc[p][j]);
        float4 lo0 = make_float4(u[0].x+bi0.x, u[1].x+bi0.y, u[2].x+bi0.z, u[3].x+bi0.w);
        float4 lo1 = make_float4(u[4].x+bi1.x, u[5].x+bi1.y, u[6].x+bi1.z, u[7].x+bi1.w);
        float4 hi0 = make_float4(u[0].y+bi0.x, u[1].y+bi0.y, u[2].y+bi0.z, u[3].y+bi0.w);
        float4 hi1 = make_float4(u[4].y+bi1.x, u[5].y+bi1.y, u[6].y+bi1.z, u[7].y+bi1.w);
        if (!SCAT || rbase < Mv) {
            size_t orow = SCAT ? (size_t)__ldg(&outIdx[rbase]) : (size_t)rbase;
            if (cok0) *(float4*)(Cout + orow * ldc + n0 + tx4)      = lo0;
            if (cok1) *(float4*)(Cout + orow * ldc + n0 + tx4 + 64) = lo1;
        }
        int rh = rbase + 1;
        if (!SCAT || rh < Mv) {
            size_t orow = SCAT ? (size_t)__ldg(&outIdx[rh]) : (size_t)rh;
            if (cok0) *(float4*)(Cout + orow * ldc + n0 + tx4)      = hi0;
            if (cok1) *(float4*)(Cout + orow * ldc + n0 + tx4 + 64) = hi1;
        }
    }
}

// ---------------------------------------------------------------------------
// tf32 word projection v3 — byte-identical to the round-11 PASSING version.
// ---------------------------------------------------------------------------
__global__ __launch_bounds__(256) void word_mma(
    const float* __restrict__ A,       // Hbuf [R][512]
    const float* __restrict__ Bm,      // word_w [V][512]
    const float* __restrict__ bias,    // word_b [V]
    float* __restrict__ Cout,          // out [R][V]
    const int* __restrict__ outIdx,    // vrow
    const int* __restrict__ MvP)       // d_S
{
    constexpr int ST = 20;                          // words per smem row
    __shared__ __align__(16) unsigned As[2][128 * ST];
    __shared__ __align__(16) unsigned Bs[2][128 * ST];

    int m0 = blockIdx.x * 128, n0 = blockIdx.y * 128;
    int Mv = __ldg(MvP);
    if (m0 >= Mv) return;

    int tid = threadIdx.x, lane = tid & 31, w = tid >> 5;
    int wm = w & 3, wn = w >> 2;        // 4m x 2n warp grid
    int lrow = tid >> 2, q = tid & 3;   // rows lrow & lrow+64, float4 slot q
    const float4 z4 = make_float4(0.f, 0.f, 0.f, 0.f);

    const float4* Ag0 = (const float4*)(A + (size_t)(m0 + lrow)      * D) + q;
    const float4* Ag1 = (const float4*)(A + (size_t)(m0 + lrow + 64) * D) + q;
    int br0 = n0 + lrow, br1 = n0 + lrow + 64;
    bool bok0 = br0 < V, bok1 = br1 < V;
    const float4* Bg0 = (const float4*)(Bm + (size_t)(bok0 ? br0 : 0) * D) + q;
    const float4* Bg1 = (const float4*)(Bm + (size_t)(bok1 ? br1 : 0) * D) + q;

    int s0 = lrow * ST + q * 4;
    int s1 = (lrow + 64) * ST + q * 4;

    float acc[2][8][4];
    #pragma unroll
    for (int i = 0; i < 2; i++)
        #pragma unroll
        for (int j = 0; j < 8; j++)
            #pragma unroll
            for (int r = 0; r < 4; r++) acc[i][j][r] = 0.f;

    float4 pa0 = __ldg(Ag0), pa1 = __ldg(Ag1);
    float4 pb0 = bok0 ? __ldg(Bg0) : z4;
    float4 pb1 = bok1 ? __ldg(Bg1) : z4;
    {
        uint4 u;
        u.x=tf32_of(pa0.x); u.y=tf32_of(pa0.y); u.z=tf32_of(pa0.z); u.w=tf32_of(pa0.w);
        *(uint4*)&As[0][s0] = u;
        u.x=tf32_of(pa1.x); u.y=tf32_of(pa1.y); u.z=tf32_of(pa1.z); u.w=tf32_of(pa1.w);
        *(uint4*)&As[0][s1] = u;
        u.x=tf32_of(pb0.x); u.y=tf32_of(pb0.y); u.z=tf32_of(pb0.z); u.w=tf32_of(pb0.w);
        *(uint4*)&Bs[0][s0] = u;
        u.x=tf32_of(pb1.x); u.y=tf32_of(pb1.y); u.z=tf32_of(pb1.z); u.w=tf32_of(pb1.w);
        *(uint4*)&Bs[0][s1] = u;
    }
    __syncthreads();

    int g = lane >> 2, t4 = lane & 3;
    const int KT = D / 16;   // 32 chunks of k=16
    for (int kt = 0; kt < KT; kt++) {
        int cur = kt & 1;
        if (kt + 1 < KT) {
            int ko = (kt + 1) * 4;
            pa0 = __ldg(Ag0 + ko); pa1 = __ldg(Ag1 + ko);
            pb0 = bok0 ? __ldg(Bg0 + ko) : z4;
            pb1 = bok1 ? __ldg(Bg1 + ko) : z4;
        }
        #pragma unroll
        for (int ks = 0; ks < 2; ks++) {
            int kb = ks * 8;
            unsigned af[2][4], bf[8][2];
            #pragma unroll
            for (int i = 0; i < 2; i++) {
                int base = (wm * 32 + i * 16 + g) * ST + kb + t4;
                af[i][0] = As[cur][base];
                af[i][1] = As[cur][base + 8 * ST];
                af[i][2] = As[cur][base + 4];
                af[i][3] = As[cur][base + 8 * ST + 4];
            }
            #pragma unroll
            for (int j = 0; j < 8; j++) {
                int base = (wn * 64 + j * 8 + g) * ST + kb + t4;
                bf[j][0] = Bs[cur][base];
                bf[j][1] = Bs[cur][base + 4];
            }
            #pragma unroll
            for (int i = 0; i < 2; i++)
                #pragma unroll
                for (int j = 0; j < 8; j++)
                    mma_tf32(acc[i][j], af[i], bf[j]);
        }
        if (kt + 1 < KT) {
            int nb = 1 - cur;
            uint4 u;
            u.x=tf32_of(pa0.x); u.y=tf32_of(pa0.y); u.z=tf32_of(pa0.z); u.w=tf32_of(pa0.w);
            *(uint4*)&As[nb][s0] = u;
            u.x=tf32_of(pa1.x); u.y=tf32_of(pa1.y); u.z=tf32_of(pa1.z); u.w=tf32_of(pa1.w);
            *(uint4*)&As[nb][s1] = u;
            u.x=tf32_of(pb0.x); u.y=tf32_of(pb0.y); u.z=tf32_of(pb0.z); u.w=tf32_of(pb0.w);
            *(uint4*)&Bs[nb][s0] = u;
            u.x=tf32_of(pb1.x); u.y=tf32_of(pb1.y); u.z=tf32_of(pb1.z); u.w=tf32_of(pb1.w);
            *(uint4*)&Bs[nb][s1] = u;
        }
        __syncthreads();
    }

    int r0 = lane >> 2, tg = lane & 3;
    #pragma unroll
    for (int i = 0; i < 2; i++) {
        #pragma unroll
        for (int h = 0; h < 2; h++) {
            int gr = m0 + wm * 32 + i * 16 + r0 + h * 8;
            if (gr < Mv) {
                size_t orow = (size_t)__ldg(&outIdx[gr]);
                float* outr = Cout + orow * V;
                #pragma unroll
                for (int j = 0; j < 8; j++) {
                    int gc = n0 + wn * 64 + j * 8 + tg * 2;
                    if (gc < V) {
                        float b0 = __ldg(&bias[gc]), b1 = __ldg(&bias[gc + 1]);
                        float2 v;
                        v.x = acc[i][j][h * 2 + 0] + b0;
                        v.y = acc[i][j][h * 2 + 1] + b1;
                        *(float2*)(outr + gc) = v;
                    }
                }
            }
        }
    }
}

// ---------------------------------------------------------------------------
__global__ void zerofill(float* __restrict__ out)
{
    int r = blockIdx.x, b = r / T, t = r - b * T;
    if (t < d_dlen[b]) return;
    float4* p = (float4*)(out + (size_t)r * V);
    float4 z = make_float4(0.f, 0.f, 0.f, 0.f);
    for (int i = threadIdx.x; i < V / 4; i += blockDim.x) p[i] = z;
}

// ---------------------------------------------------------------------------
// persistent LSTM: ONE change vs round-11 — compute remap to 2 rows x 4 cols
// per thread (rp = tid>>2, c4 = tid&3). Per k: 1 LDS.64 (row pair) + 1
// LDS.128 (4 w cols) feed 8 FMAs -> ~9x less smem read traffic (the
// crossbar was the binding resource). Same k-order per (row,col) =>
// bit-identical results. Loads/prefetch/barrier/pointwise unchanged.
// ---------------------------------------------------------------------------
__global__ __launch_bounds__(256) void lstm_persist(const float* __restrict__ w_hh)
{
    __shared__ float w_s[512][16];
    __shared__ __align__(16) float hs[16][132];
    __shared__ float c_s[512];
    __shared__ int s_start[NB];
    __shared__ int s_nt[T];

    int tid = threadIdx.x, d0 = blockIdx.x * 4;

    #pragma unroll
    for (int s = 0; s < 8; s++) {
        int lin = tid + s * 256;
        int i = lin >> 7, q = lin & 127;
        int gc = (i >> 2) * 512 + d0 + (i & 3);
        float4 v = __ldg((const float4*)(w_hh + (size_t)gc * 512 + q * 4));
        w_s[q*4+0][i]=v.x; w_s[q*4+1][i]=v.y; w_s[q*4+2][i]=v.z; w_s[q*4+3][i]=v.w;
    }
    if (tid < NB) s_start[tid] = d_start[tid];
    if (tid < T)  s_nt[tid] = d_nt[tid];
    for (int e = tid; e < 512; e += 256) c_s[e] = 0.f;
    __syncthreads();

    int rp = tid >> 2, c4 = tid & 3;     // compute tile: rows 2rp,2rp+1 x cols 4c4..+3
    int row0 = tid >> 2, q2 = tid & 3;   // load jobs (same partition, reused)
    int row1 = row0 + 64;

    for (int t = 0; t < T; t++) {
        int nt = s_nt[t];
        int nt8 = (nt + 7) & ~7;
        bool cok = (2 * rp) < nt8;
        bool l0 = row0 < nt8, l1 = row1 < nt8;
        const float* hc = (t & 1) ? d_hB : d_hA;
        float*       hw = (t & 1) ? d_hA : d_hB;

        unsigned long long acc[4] = {0ull, 0ull, 0ull, 0ull};

        float4 v0, v1;                    // prefetch chunk 0
        if (l0) v0 = __ldcg((const float4*)(hc + (size_t)row0 * 512 + q2 * 4));
        if (l1) v1 = __ldcg((const float4*)(hc + (size_t)row1 * 512 + q2 * 4));

        for (int kc = 0; kc < 32; kc++) {
            if (l0) { hs[q2*4+0][row0]=v0.x; hs[q2*4+1][row0]=v0.y; hs[q2*4+2][row0]=v0.z; hs[q2*4+3][row0]=v0.w; }
            if (l1) { hs[q2*4+0][row1]=v1.x; hs[q2*4+1][row1]=v1.y; hs[q2*4+2][row1]=v1.z; hs[q2*4+3][row1]=v1.w; }
            __syncthreads();
            if (kc + 1 < 32) {
                int ko = (kc + 1) * 16 + q2 * 4;
                if (l0) v0 = __ldcg((const float4*)(hc + (size_t)row0 * 512 + ko));
                if (l1) v1 = __ldcg((const float4*)(hc + (size_t)row1 * 512 + ko));
            }
            if (cok) {
                #pragma unroll
                for (int k = 0; k < 16; k++) {
                    unsigned long long hp = *(const unsigned long long*)&hs[k][rp * 2];
                    float4 wv = *(const float4*)&w_s[kc * 16 + k][c4 * 4];
                    fma2(acc[0], hp, dup2(wv.x));
                    fma2(acc[1], hp, dup2(wv.y));
                    fma2(acc[2], hp, dup2(wv.z));
                    fma2(acc[3], hp, dup2(wv.w));
                }
            }
            __syncthreads();
        }
        // stash gates: gs[col][batchrow] in hs
        #pragma unroll
        for (int j = 0; j < 4; j++) {
            float2 f = unpk(acc[j]);
            hs[c4 * 4 + j][rp * 2 + 0] = f.x;
            hs[c4 * 4 + j][rp * 2 + 1] = f.y;
        }
        __syncthreads();
        for (int e = tid; e < 512; e += 256) {
            int b = e >> 2, dd = e & 3;
            if (b < nt) {
                size_t cidx = (size_t)(s_start[b] + t);
                const float* xp = d_xproj + cidx * G + d0 + dd;
                float g0 = hs[dd][b]      + __ldg(xp);
                float g1 = hs[4 + dd][b]  + __ldg(xp + 512);
                float g2 = hs[8 + dd][b]  + __ldg(xp + 1024);
                float g3 = hs[12 + dd][b] + __ldg(xp + 1536);
                float gi = 1.f / (1.f + __expf(-g0));
                float gf = 1.f / (1.f + __expf(-g1));
                float gg = tanhf(g2);
                float go = 1.f / (1.f + __expf(-g3));
                float c  = c_s[e];
                float cn = gf * c + gi * gg;
                float hn = go * tanhf(cn);
                c_s[e] = cn;
                __stcg(hw + (size_t)b * 512 + d0 + dd, hn);
                d_Hbuf[cidx * 512 + d0 + dd] = hn;
            }
        }
        if (t < T - 1) {
            int tg2 = t + 1;
            __syncthreads();
            if (tid == 0) { __threadfence(); d_flags2[blockIdx.x] = tg2; }
            if (blockIdx.x == 0) {
                if (tid < NB) { while (d_flags2[tid] < tg2) __nanosleep(32); }
                __syncthreads();
                if (tid == 0) { __threadfence(); d_gen2 = tg2; }
            }
            if (tid == 0) { while (d_gen2 < tg2) __nanosleep(32); __threadfence(); }
            __syncthreads();
        }
    }
}

// ---------------------------------------------------------------------------
extern "C" void kernel_launch(void* const* d_in, const int* in_sizes, int n_in,
                              void* d_out, int out_size)
{
    const float* feats  = (const float*)d_in[0];
    const int*   caps   = (const int*)  d_in[1];
    const int*   clen   = (const int*)  d_in[2];
    const float* emb    = (const float*)d_in[3];
    const float* att1_w = (const float*)d_in[4];
    const float* att1_b = (const float*)d_in[5];
    const float* w_ih   = (const float*)d_in[6];
    const float* w_hh   = (const float*)d_in[7];
    const float* b_ih   = (const float*)d_in[8];
    const float* b_hh   = (const float*)d_in[9];
    const float* word_w = (const float*)d_in[10];
    const float* word_b = (const float*)d_in[11];
    float* out = (float*)d_out;

    float *xproj, *Hbuf, *bias2;
    int *tok, *vrow, *Sp;
    cudaGetSymbolAddress((void**)&xproj, d_xproj);
    cudaGetSymbolAddress((void**)&Hbuf,  d_Hbuf);
    cudaGetSymbolAddress((void**)&bias2, d_bias2);
    cudaGetSymbolAddress((void**)&tok,   d_tok);
    cudaGetSymbolAddress((void**)&vrow,  d_vrow);
    cudaGetSymbolAddress((void**)&Sp,    d_S);

    const long long PRED = (long long)NB * T * V;
    int write_tail = ((long long)out_size >= PRED + NB * L + 2 * NB) ? 1 : 0;

    prep_kernel<<<1, NB>>>(clen, caps, b_ih, b_hh, out, write_tail);
    mean_kernel<<<NB, 256>>>(feats);
    h0_kernel<<<dim3(NB, 4), 256>>>(att1_w, att1_b);

    // xproj (compacted rows): emb[tok] @ w_ih^T + (b_ih+b_hh)
    gemm128<true, false><<<dim3(R / 128, G / 128), 256>>>(
        emb, E, tok, w_ih, bias2, xproj, G, nullptr, Sp, G, E);

    zerofill<<<R, 256>>>(out);

    lstm_persist<<<NB, 256>>>(w_hh);

    // word projection: tf32 tensor cores, 128x128 tiles, scatter to out
    word_mma<<<dim3((R + 127) / 128, (V + 127) / 128), 256>>>(
        Hbuf, word_w, word_b, out, vrow, Sp);
}